// round 6
// baseline (speedup 1.0000x reference)
#include <cuda_runtime.h>
#include <cuda_bf16.h>
#include <stdint.h>
#include <math.h>

#define ND 96
#define ED 64
#define KD 256
#define TM 128          // edges per tile (MMA M)
#define NTOT 192        // fused output cols (We|Wn)
#define BLK 384
#define MAXN (1<<17)
#define EMAX (1<<20)

__device__ int g_hist[MAXN];
__device__ int g_cursor[MAXN];
__device__ int g_ssrc[EMAX];
__device__ int g_sdst[EMAX];
__device__ int g_perm[EMAX];
__device__ int g_is64;

// ---- smem layout ----
#define SB_OFF   0          // B tile: 192x256 bf16 blocked SW128 (98304)
#define SA_OFF   98304      // A tile: 128x256 bf16 (65536)
#define ACT_OFF  163840     // act staging: 128 rows x 100 floats (51200)
#define SIDX_OFF 215040     // src[128] | dst[128] | perm[128] (1536)
#define SMEM_REQ 216576
#define ACT_STRIDE 100

#define SW128(o) ((o) ^ (((o) >> 3) & 0x70))

__device__ __forceinline__ uint32_t smem_u32(const void* p) {
    uint32_t r;
    asm("{ .reg .u64 t; cvta.to.shared.u64 t, %1; cvt.u32.u64 %0, t; }"
        : "=r"(r) : "l"(p));
    return r;
}
__device__ __forceinline__ void ldsm_x4(uint32_t* r, uint32_t addr) {
    asm volatile("ldmatrix.sync.aligned.m8n8.x4.shared.b16 {%0,%1,%2,%3}, [%4];"
        : "=r"(r[0]), "=r"(r[1]), "=r"(r[2]), "=r"(r[3]) : "r"(addr));
}
__device__ __forceinline__ void mma16816(float* c, const uint32_t* a, const uint32_t* b) {
    asm volatile("mma.sync.aligned.m16n8k16.row.col.f32.bf16.bf16.f32 "
        "{%0,%1,%2,%3}, {%4,%5,%6,%7}, {%8,%9}, {%0,%1,%2,%3};"
        : "+f"(c[0]), "+f"(c[1]), "+f"(c[2]), "+f"(c[3])
        : "r"(a[0]), "r"(a[1]), "r"(a[2]), "r"(a[3]), "r"(b[0]), "r"(b[1]));
}

__device__ __forceinline__ float act_gm(float xg, float xn) {
    float t;
    asm("tanh.approx.f32 %0, %1;" : "=f"(t) : "f"(xg * 0.5f));
    float gate = fmaf(t, 0.5f, 0.5f);
    float p;
    asm("ex2.approx.f32 %0, %1;" : "=f"(p) : "f"(-fabsf(xn) * 1.4426950408889634f));
    float l;
    asm("lg2.approx.f32 %0, %1;" : "=f"(l) : "f"(1.0f + p));
    float sp = fmaxf(xn, 0.0f) + 0.69314718055994531f * l;
    return gate * sp;
}

// ---------------- prep kernels ----------------
__global__ void init_kernel(float4* __restrict__ out4, const uint32_t* __restrict__ ew,
                            long long total4, int n, long long nwords) {
    long long i = (long long)blockIdx.x * blockDim.x + threadIdx.x;
    if (i < total4) out4[i] = make_float4(0.f, 0.f, 0.f, 0.f);
    if (i < n) g_hist[i] = 0;
    if (i == 0) {
        int is64 = 1;
        long long m = nwords < 256 ? nwords : 256;
        for (long long w = 1; w < m; w += 2)
            if (ew[w] != 0u) { is64 = 0; break; }
        g_is64 = is64;
    }
}

__global__ void hist_kernel(const void* __restrict__ eidx, int E) {
    int e = blockIdx.x * blockDim.x + threadIdx.x;
    if (e >= E) return;
    int d = g_is64 ? (int)((const long long*)eidx)[(long long)E + e]
                   : ((const int*)eidx)[(long long)E + e];
    atomicAdd(&g_hist[d], 1);
}

__global__ void scan_kernel(int n) {
    __shared__ int part[1024];
    const int tid = threadIdx.x;
    int chunk = (n + 1023) >> 10;
    int lo = tid * chunk;
    int hi = lo + chunk; if (hi > n) hi = n; if (lo > n) lo = n;
    int s = 0;
    for (int i = lo; i < hi; i++) s += g_hist[i];
    part[tid] = s;
    __syncthreads();
    for (int ofs = 1; ofs < 1024; ofs <<= 1) {
        int v = (tid >= ofs) ? part[tid - ofs] : 0;
        __syncthreads();
        part[tid] += v;
        __syncthreads();
    }
    int run = (tid > 0) ? part[tid - 1] : 0;
    for (int i = lo; i < hi; i++) {
        g_cursor[i] = run;
        run += g_hist[i];
    }
}

__global__ void perm_kernel(const void* __restrict__ eidx, int E) {
    int e = blockIdx.x * blockDim.x + threadIdx.x;
    if (e >= E) return;
    int s, d;
    if (g_is64) {
        s = (int)((const long long*)eidx)[e];
        d = (int)((const long long*)eidx)[(long long)E + e];
    } else {
        s = ((const int*)eidx)[e];
        d = ((const int*)eidx)[(long long)E + e];
    }
    int pos = atomicAdd(&g_cursor[d], 1);
    g_ssrc[pos] = s;
    g_sdst[pos] = d;
    g_perm[pos] = e;
}

__global__ void finalize_kernel(const float4* __restrict__ h4, float4* __restrict__ out4,
                                long long total4) {
    long long i = (long long)blockIdx.x * blockDim.x + threadIdx.x;
    if (i < total4) {
        int node = (int)(i / (ND / 4));
        float c = (float)g_hist[node];
        c = c < 1.0f ? 1.0f : c;
        float inv = 1.0f / c;
        float4 a = h4[i], b = out4[i];
        out4[i] = make_float4(a.x + b.x * inv, a.y + b.y * inv,
                              a.z + b.z * inv, a.w + b.w * inv);
    }
}

// ---------------- main edge kernel ----------------
__global__ __launch_bounds__(BLK, 1)
void edge_kernel(const float* __restrict__ h,
                 const float* __restrict__ edge_attr,
                 const float* __restrict__ W_e, const float* __restrict__ b_e,
                 const float* __restrict__ W_n, const float* __restrict__ b_n,
                 float* __restrict__ out, int E, int ntiles) {
    extern __shared__ char sm[];
    const uint32_t sbase = smem_u32(sm);

    const int tid = threadIdx.x;
    const int wid = tid >> 5;
    const int lane = tid & 31;
    const int wmr = wid & 1;          // row half: rows [64*wmr, 64*wmr+64)
    const int wnc = wid >> 1;         // 0..5: gate cols [16*wnc,+16), msg cols +96

    // B tile: rows n<96 = W_e col n; n>=96 = W_n col n-96.  [n][k] bf16, blocked SW128.
    for (int idx = tid; idx < NTOT * (KD / 2); idx += BLK) {
        int n = idx >> 7;
        int k = (idx & 127) * 2;
        const float* W = (n < ND) ? W_e : W_n;
        int col = (n < ND) ? n : n - ND;
        float f0 = W[k * ND + col];
        float f1 = W[(k + 1) * ND + col];
        __nv_bfloat162 p = __floats2bfloat162_rn(f0, f1);
        uint32_t off = (uint32_t)(k >> 6) * 24576u + (uint32_t)(n >> 3) * 1024u
                     + (uint32_t)(n & 7) * 128u + (uint32_t)(k & 63) * 2u;
        *(uint32_t*)(sm + SB_OFF + SW128(off)) = *(uint32_t*)&p;
    }

    // per-lane bias registers
    const int tt = lane & 3;
    float bgc[2][2], bnc[2][2];
    #pragma unroll
    for (int j = 0; j < 2; j++) {
        int c0 = 16 * wnc + 8 * j + 2 * tt;
        bgc[j][0] = b_e[c0];     bgc[j][1] = b_e[c0 + 1];
        bnc[j][0] = b_n[c0];     bnc[j][1] = b_n[c0 + 1];
    }

    int* sI = (int*)(sm + SIDX_OFF);      // src[128] | dst[128] | perm[128]
    float* ACT = (float*)(sm + ACT_OFF);

    // --- per-lane ldmatrix constants ---
    const int a_m = lane >> 3;
    const int a_erow = ((a_m & 1) << 3) + (lane & 7);
    const int a_khalf = a_m >> 1;
    const int b_m = lane >> 3;
    const int b_nrow = ((b_m & 2) << 2) + (lane & 7);
    const int b_khalf = b_m & 1;

    const uint32_t saA = sbase + SA_OFF;
    const uint32_t saB = sbase + SB_OFF;
    const int ng0 = 16 * wnc;
    const int ng = ng0 + b_nrow;
    const int nm = ng + ND;
    const uint32_t bgBase = saB + (uint32_t)(ng >> 3) * 1024u + (uint32_t)(ng & 7) * 128u;
    const uint32_t bgSw = (uint32_t)(ng & 7);
    const uint32_t bmBase = saB + (uint32_t)(nm >> 3) * 1024u + (uint32_t)(nm & 7) * 128u;
    const uint32_t bmSw = (uint32_t)(nm & 7);

    uint32_t aBase[4], aSw[4];
    #pragma unroll
    for (int i = 0; i < 4; i++) {
        int e = 64 * wmr + 16 * i + a_erow;
        aBase[i] = saA + (uint32_t)(e >> 3) * 1024u + (uint32_t)(e & 7) * 128u;
        aSw[i] = (uint32_t)(e & 7);
    }

    // aggregation mapping: thread -> (col, row quarter); warp-uniform q and dst runs
    const int aq = tid / ND;
    const int ac = tid - aq * ND;
    const int gg = lane >> 2;

    const int grid = gridDim.x;
    const int bid = blockIdx.x;

    for (int t = bid; t < ntiles; t += grid) {
        int ebase = t * TM;
        __syncthreads();   // prev tile's ACT/sI fully consumed

        {
            int which = tid >> 7;           // 0=src 1=dst 2=perm
            int e = tid & 127;
            int eg = ebase + e;
            int v;
            if (eg < E)
                v = (which == 0) ? g_ssrc[eg] : (which == 1) ? g_sdst[eg] : g_perm[eg];
            else
                v = (which == 2) ? 0 : -1;
            sI[tid] = v;
        }
        __syncthreads();

        // gather + convert into A tile (blocked SW128, bf16)
        #pragma unroll 4
        for (int idx = tid; idx < TM * (KD / 4); idx += BLK) {
            int e = idx >> 6;
            int k = (idx & 63) * 4;
            int src = sI[e];
            float4 x = make_float4(0.f, 0.f, 0.f, 0.f);
            if (src >= 0) {
                if (k < ND)
                    x = *(const float4*)(h + (long long)src * ND + k);
                else if (k < 2 * ND)
                    x = *(const float4*)(h + (long long)sI[TM + e] * ND + (k - ND));
                else
                    x = *(const float4*)(edge_attr + (long long)sI[2 * TM + e] * ED + (k - 2 * ND));
            }
            __nv_bfloat162 p0 = __floats2bfloat162_rn(x.x, x.y);
            __nv_bfloat162 p1 = __floats2bfloat162_rn(x.z, x.w);
            uint2 u = make_uint2(*(uint32_t*)&p0, *(uint32_t*)&p1);
            uint32_t off = (uint32_t)(k >> 6) * 16384u + (uint32_t)(e >> 3) * 1024u
                         + (uint32_t)(e & 7) * 128u + (uint32_t)(k & 63) * 2u;
            *(uint2*)(sm + SA_OFF + SW128(off)) = u;
        }
        __syncthreads();

        // ---- GEMM: warp tile = 64 rows x (16 gate + 16 msg) cols ----
        float cg[4][2][4], cmsg[4][2][4];
        #pragma unroll
        for (int i = 0; i < 4; i++)
            #pragma unroll
            for (int j = 0; j < 2; j++)
                #pragma unroll
                for (int c = 0; c < 4; c++) { cg[i][j][c] = 0.f; cmsg[i][j][c] = 0.f; }

        #pragma unroll 4
        for (int kc = 0; kc < 16; kc++) {
            uint32_t kblkA = (uint32_t)(kc >> 2) * 16384u;
            uint32_t kblkB = (uint32_t)(kc >> 2) * 24576u;
            uint32_t kc2 = (uint32_t)((kc & 3) << 1);

            uint32_t aF[4][4];
            #pragma unroll
            for (int i = 0; i < 4; i++) {
                uint32_t chunk = ((kc2 | (uint32_t)a_khalf) ^ aSw[i]) << 4;
                ldsm_x4(aF[i], kblkA + aBase[i] + chunk);
            }
            uint32_t bg[4], bm[4];
            {
                uint32_t cg_ = ((kc2 | (uint32_t)b_khalf) ^ bgSw) << 4;
                ldsm_x4(bg, kblkB + bgBase + cg_);
                uint32_t cm_ = ((kc2 | (uint32_t)b_khalf) ^ bmSw) << 4;
                ldsm_x4(bm, kblkB + bmBase + cm_);
            }
            #pragma unroll
            for (int i = 0; i < 4; i++) {
                mma16816(cg[i][0], aF[i], bg);
                mma16816(cg[i][1], aF[i], bg + 2);
                mma16816(cmsg[i][0], aF[i], bm);
                mma16816(cmsg[i][1], aF[i], bm + 2);
            }
        }

        // ---- activations -> ACT staging buffer ----
        #pragma unroll
        for (int i = 0; i < 4; i++) {
            int row0 = 64 * wmr + 16 * i + gg;
            int row1 = row0 + 8;
            #pragma unroll
            for (int j = 0; j < 2; j++) {
                int c0 = ng0 + 8 * j + 2 * tt;
                float v00 = act_gm(cg[i][j][0] + bgc[j][0], cmsg[i][j][0] + bnc[j][0]);
                float v01 = act_gm(cg[i][j][1] + bgc[j][1], cmsg[i][j][1] + bnc[j][1]);
                float v10 = act_gm(cg[i][j][2] + bgc[j][0], cmsg[i][j][2] + bnc[j][0]);
                float v11 = act_gm(cg[i][j][3] + bgc[j][1], cmsg[i][j][3] + bnc[j][1]);
                *(float2*)(ACT + row0 * ACT_STRIDE + c0) = make_float2(v00, v01);
                *(float2*)(ACT + row1 * ACT_STRIDE + c0) = make_float2(v10, v11);
            }
        }
        __syncthreads();

        // ---- segmented sum over sorted dst runs; flush boundaries with RED ----
        {
            int r0 = 32 * aq;
            float acc = 0.0f;
            int dcur = sI[TM + r0];
            #pragma unroll 8
            for (int r = r0; r < r0 + 32; r++) {
                int d = sI[TM + r];
                float v = ACT[r * ACT_STRIDE + ac];
                if (d != dcur) {
                    if (dcur >= 0) {
                        asm volatile("red.global.add.f32 [%0], %1;"
                            :: "l"(out + (long long)dcur * ND + ac), "f"(acc) : "memory");
                    }
                    acc = 0.0f;
                    dcur = d;
                }
                acc += v;
            }
            if (dcur >= 0) {
                asm volatile("red.global.add.f32 [%0], %1;"
                    :: "l"(out + (long long)dcur * ND + ac), "f"(acc) : "memory");
            }
        }
    }
}

extern "C" void kernel_launch(void* const* d_in, const int* in_sizes, int n_in,
                              void* d_out, int out_size) {
    const float* h   = (const float*)d_in[0];
    const void*  ei  = d_in[1];
    const float* ea  = (const float*)d_in[2];
    const float* W_e = (const float*)d_in[3];
    const float* b_e = (const float*)d_in[4];
    const float* W_n = (const float*)d_in[5];
    const float* b_n = (const float*)d_in[6];
    float* out = (float*)d_out;

    int N = in_sizes[0] / ND;
    int E = in_sizes[2] / ED;
    long long total4 = (long long)N * ND / 4;
    long long nwords = (long long)in_sizes[1];

    int ib = (int)((total4 + 255) / 256);
    init_kernel<<<ib, 256>>>((float4*)out, (const uint32_t*)ei, total4, N, nwords);

    int eb = (E + 255) / 256;
    hist_kernel<<<eb, 256>>>(ei, E);
    scan_kernel<<<1, 1024>>>(N);
    perm_kernel<<<eb, 256>>>(ei, E);

    int ntiles = (E + TM - 1) / TM;
    cudaFuncSetAttribute(edge_kernel, cudaFuncAttributeMaxDynamicSharedMemorySize, SMEM_REQ);
    int grid = ntiles < 148 ? ntiles : 148;
    edge_kernel<<<grid, BLK, SMEM_REQ>>>(h, ea, W_e, b_e, W_n, b_n, out, E, ntiles);

    finalize_kernel<<<ib, 256>>>((const float4*)h, (float4*)out, total4);
}

// round 7
// speedup vs baseline: 1.4865x; 1.4865x over previous
#include <cuda_runtime.h>
#include <cuda_bf16.h>
#include <stdint.h>
#include <math.h>

#define ND 96
#define ED 64
#define TM 128            // edges per tile
#define BLK 768           // edge kernel threads (24 warps)
#define ABLK 512          // node kernel threads
#define MAXN 65536

__device__ __nv_bfloat16 g_P1[(size_t)MAXN * 192];   // h*W_src + bias (gate|msg)
__device__ __nv_bfloat16 g_P2[(size_t)MAXN * 192];   // h*W_dst
__device__ float g_cnt[MAXN];
__device__ int g_is64;

// ---- edge kernel smem layout ----
#define E_B3 0            // 192x64 bf16 blocked SW128 (24576)
#define E_A0 24576        // A3 buf0: 128x64 bf16 (16384)
#define E_A1 40960        // A3 buf1 (16384)
#define E_PS 57344        // PS: 128 x 194 fp32 (99328)
#define E_SI 156672       // 3 x (src[128]|dst[128]) (3072)
#define E_SMEM 159744
#define PS_STRIDE 194

// ---- node kernel smem ----
#define N_B 0             // 384x96(k pad 128) bf16 blocked (98304)
#define N_A 98304         // 64x96(pad 128) bf16 (16384)
#define N_SMEM 114688

#define SW128(o) ((o) ^ (((o) >> 3) & 0x70))

__device__ __forceinline__ uint32_t smem_u32(const void* p) {
    uint32_t r;
    asm("{ .reg .u64 t; cvta.to.shared.u64 t, %1; cvt.u32.u64 %0, t; }"
        : "=r"(r) : "l"(p));
    return r;
}
__device__ __forceinline__ void ldsm_x4(uint32_t* r, uint32_t addr) {
    asm volatile("ldmatrix.sync.aligned.m8n8.x4.shared.b16 {%0,%1,%2,%3}, [%4];"
        : "=r"(r[0]), "=r"(r[1]), "=r"(r[2]), "=r"(r[3]) : "r"(addr));
}
__device__ __forceinline__ void mma16816(float* c, const uint32_t* a, const uint32_t* b) {
    asm volatile("mma.sync.aligned.m16n8k16.row.col.f32.bf16.bf16.f32 "
        "{%0,%1,%2,%3}, {%4,%5,%6,%7}, {%8,%9}, {%0,%1,%2,%3};"
        : "+f"(c[0]), "+f"(c[1]), "+f"(c[2]), "+f"(c[3])
        : "r"(a[0]), "r"(a[1]), "r"(a[2]), "r"(a[3]), "r"(b[0]), "r"(b[1]));
}
__device__ __forceinline__ float act_gm(float xg, float xn) {
    float t;
    asm("tanh.approx.f32 %0, %1;" : "=f"(t) : "f"(xg * 0.5f));
    float gate = fmaf(t, 0.5f, 0.5f);
    float p;
    asm("ex2.approx.f32 %0, %1;" : "=f"(p) : "f"(-fabsf(xn) * 1.4426950408889634f));
    float l;
    asm("lg2.approx.f32 %0, %1;" : "=f"(l) : "f"(1.0f + p));
    float sp = fmaxf(xn, 0.0f) + 0.69314718055994531f * l;
    return gate * sp;
}
__device__ __forceinline__ float2 bfadd2(uint32_t a, uint32_t b) {
    float2 fa = __bfloat1622float2(*(__nv_bfloat162*)&a);
    float2 fb = __bfloat1622float2(*(__nv_bfloat162*)&b);
    return make_float2(fa.x + fb.x, fa.y + fb.y);
}

// ---------------- init / finalize ----------------
__global__ void init_kernel(float4* __restrict__ out4, const uint32_t* __restrict__ ew,
                            long long total4, int n, long long nwords) {
    long long i = (long long)blockIdx.x * blockDim.x + threadIdx.x;
    if (i < total4) out4[i] = make_float4(0.f, 0.f, 0.f, 0.f);
    if (i < n) g_cnt[i] = 0.0f;
    if (i == 0) {
        int is64 = 1;
        long long m = nwords < 256 ? nwords : 256;
        for (long long w = 1; w < m; w += 2)
            if (ew[w] != 0u) { is64 = 0; break; }
        g_is64 = is64;
    }
}

__global__ void finalize_kernel(const float4* __restrict__ h4, float4* __restrict__ out4,
                                long long total4) {
    long long i = (long long)blockIdx.x * blockDim.x + threadIdx.x;
    if (i < total4) {
        int node = (int)(i / (ND / 4));
        float c = g_cnt[node];
        c = c < 1.0f ? 1.0f : c;
        float inv = 1.0f / c;
        float4 a = h4[i], b = out4[i];
        out4[i] = make_float4(a.x + b.x * inv, a.y + b.y * inv,
                              a.z + b.z * inv, a.w + b.w * inv);
    }
}

// ---------------- node precompute kernel ----------------
// P[node][384] = h[node][0:96] @ Wcat[96][384], cols: [P1 gate|P1 msg|P2 gate|P2 msg]
__global__ __launch_bounds__(ABLK, 1)
void node_kernel(const float* __restrict__ h,
                 const float* __restrict__ W_e, const float* __restrict__ b_e,
                 const float* __restrict__ W_n, const float* __restrict__ b_n, int N) {
    extern __shared__ char sm[];
    const uint32_t sbase = smem_u32(sm);
    const int tid = threadIdx.x;
    const int wid = tid >> 5, lane = tid & 31;
    const int rg = wid & 1, cg = wid >> 1;   // 2 row groups x 8 col groups (48 cols)
    const int na0 = blockIdx.x * 64;

    // B = Wcat: n in [0,384): q0 We[k][n], q1 Wn[k][n-96], q2 We[96+k][n-192], q3 Wn[96+k][n-288]
    for (int idx = tid; idx < 384 * 64; idx += ABLK) {
        int n = idx >> 6, kp = idx & 63;
        if (kp < 48) {
            int k = kp * 2;
            float f0, f1;
            if (n < 96)       { f0 = W_e[k * 96 + n];             f1 = W_e[(k + 1) * 96 + n]; }
            else if (n < 192) { f0 = W_n[k * 96 + (n - 96)];      f1 = W_n[(k + 1) * 96 + (n - 96)]; }
            else if (n < 288) { f0 = W_e[(96 + k) * 96 + (n - 192)]; f1 = W_e[(97 + k) * 96 + (n - 192)]; }
            else              { f0 = W_n[(96 + k) * 96 + (n - 288)]; f1 = W_n[(97 + k) * 96 + (n - 288)]; }
            __nv_bfloat162 p = __floats2bfloat162_rn(f0, f1);
            uint32_t off = (uint32_t)(kp >> 5) * 49152u + (uint32_t)(n >> 3) * 1024u
                         + (uint32_t)(n & 7) * 128u + (uint32_t)(k & 63) * 2u;
            *(uint32_t*)(sm + N_B + SW128(off)) = *(uint32_t*)&p;
        }
    }
    // A = h tile (64 nodes x 96 k)
    for (int idx = tid; idx < 64 * 64; idx += ABLK) {
        int r = idx >> 6, kp = idx & 63;
        if (kp < 48) {
            int k = kp * 2, node = na0 + r;
            float f0 = 0.f, f1 = 0.f;
            if (node < N) { f0 = h[node * 96 + k]; f1 = h[node * 96 + k + 1]; }
            __nv_bfloat162 p = __floats2bfloat162_rn(f0, f1);
            uint32_t off = (uint32_t)(kp >> 5) * 8192u + (uint32_t)(r >> 3) * 1024u
                         + (uint32_t)(r & 7) * 128u + (uint32_t)(k & 63) * 2u;
            *(uint32_t*)(sm + N_A + SW128(off)) = *(uint32_t*)&p;
        }
    }
    __syncthreads();

    const int a_m = lane >> 3;
    const int a_erow = ((a_m & 1) << 3) + (lane & 7);
    const int a_khalf = a_m >> 1;
    const int b_nrow = ((a_m & 2) << 2) + (lane & 7);
    const int b_khalf = a_m & 1;

    uint32_t aBase[2], aSw[2];
    #pragma unroll
    for (int i = 0; i < 2; i++) {
        int e = 32 * rg + 16 * i + a_erow;
        aBase[i] = sbase + N_A + (uint32_t)(e >> 3) * 1024u + (uint32_t)(e & 7) * 128u;
        aSw[i] = (uint32_t)(e & 7);
    }
    uint32_t bBase[3], bSw[3];
    #pragma unroll
    for (int nb = 0; nb < 3; nb++) {
        int n = 48 * cg + 16 * nb + b_nrow;
        bBase[nb] = sbase + N_B + (uint32_t)(n >> 3) * 1024u + (uint32_t)(n & 7) * 128u;
        bSw[nb] = (uint32_t)(n & 7);
    }

    float acc[2][6][4];
    #pragma unroll
    for (int i = 0; i < 2; i++)
        #pragma unroll
        for (int b = 0; b < 6; b++)
            #pragma unroll
            for (int c = 0; c < 4; c++) acc[i][b][c] = 0.f;

    #pragma unroll
    for (int kc = 0; kc < 6; kc++) {
        uint32_t kblkA = (uint32_t)(kc >> 2) * 8192u;
        uint32_t kblkB = (uint32_t)(kc >> 2) * 49152u;
        uint32_t kc2 = (uint32_t)((kc & 3) << 1);
        uint32_t aF[2][4], bF[3][4];
        #pragma unroll
        for (int i = 0; i < 2; i++)
            ldsm_x4(aF[i], kblkA + aBase[i] + ((((kc2 | (uint32_t)a_khalf) ^ aSw[i])) << 4));
        #pragma unroll
        for (int nb = 0; nb < 3; nb++)
            ldsm_x4(bF[nb], kblkB + bBase[nb] + ((((kc2 | (uint32_t)b_khalf) ^ bSw[nb])) << 4));
        #pragma unroll
        for (int i = 0; i < 2; i++)
            #pragma unroll
            for (int nb = 0; nb < 3; nb++) {
                mma16816(acc[i][2 * nb], aF[i], bF[nb]);
                mma16816(acc[i][2 * nb + 1], aF[i], bF[nb] + 2);
            }
    }

    // store (bias folded into P1 only)
    const int gg = lane >> 2, tt = lane & 3;
    #pragma unroll
    for (int i = 0; i < 2; i++) {
        int lr0 = 32 * rg + 16 * i + gg;
        int n0 = na0 + lr0, n1 = n0 + 8;
        #pragma unroll
        for (int b = 0; b < 6; b++) {
            int cn = 48 * cg + 8 * b + 2 * tt;
            float bias0 = 0.f, bias1 = 0.f;
            if (cn < 96)       { bias0 = b_e[cn];      bias1 = b_e[cn + 1]; }
            else if (cn < 192) { bias0 = b_n[cn - 96]; bias1 = b_n[cn - 95]; }
            __nv_bfloat16* arr = (cn < 192) ? g_P1 : g_P2;
            int cc = (cn < 192) ? cn : cn - 192;
            __nv_bfloat162 v0 = __floats2bfloat162_rn(acc[i][b][0] + bias0, acc[i][b][1] + bias1);
            __nv_bfloat162 v1 = __floats2bfloat162_rn(acc[i][b][2] + bias0, acc[i][b][3] + bias1);
            if (n0 < N) *(__nv_bfloat162*)(arr + (size_t)n0 * 192 + cc) = v0;
            if (n1 < N) *(__nv_bfloat162*)(arr + (size_t)n1 * 192 + cc) = v1;
        }
    }
}

// ---------------- edge kernel ----------------
__global__ __launch_bounds__(BLK, 1)
void edge_kernel(const void* __restrict__ eidx,
                 const float* __restrict__ edge_attr,
                 const float* __restrict__ W_e, const float* __restrict__ W_n,
                 float* __restrict__ out, int E, int ntiles) {
    extern __shared__ char sm[];
    const uint32_t sbase = smem_u32(sm);
    const int tid = threadIdx.x;
    const int wid = tid >> 5, lane = tid & 31;
    const int rg = wid & 3;          // rows [32*rg, 32*rg+32)
    const int cg = wid >> 2;         // 0..5: gate cols [16cg,+16), msg +96

    // B3 = W3 (rows 192..255 of We/Wn), [n][k] bf16 blocked SW128
    for (int idx = tid; idx < 192 * 32; idx += BLK) {
        int n = idx >> 5;
        int k = (idx & 31) * 2;
        float f0, f1;
        if (n < 96) { f0 = W_e[(192 + k) * 96 + n];        f1 = W_e[(193 + k) * 96 + n]; }
        else        { f0 = W_n[(192 + k) * 96 + (n - 96)]; f1 = W_n[(193 + k) * 96 + (n - 96)]; }
        __nv_bfloat162 p = __floats2bfloat162_rn(f0, f1);
        uint32_t off = (uint32_t)(n >> 3) * 1024u + (uint32_t)(n & 7) * 128u + (uint32_t)k * 2u;
        *(uint32_t*)(sm + E_B3 + SW128(off)) = *(uint32_t*)&p;
    }

    const int is64 = g_is64;
    const long long* e64 = (const long long*)eidx;
    const int*       e32 = (const int*)eidx;
    int* sI = (int*)(sm + E_SI);
    float* PS = (float*)(sm + E_PS);

    const int a_m = lane >> 3;
    const int a_erow = ((a_m & 1) << 3) + (lane & 7);
    const int a_khalf = a_m >> 1;
    const int b_nrow = ((a_m & 2) << 2) + (lane & 7);
    const int b_khalf = a_m & 1;

    const int ng0 = 16 * cg;
    const int ng = ng0 + b_nrow;
    const int nm = ng + ND;
    const uint32_t bgBase = sbase + E_B3 + (uint32_t)(ng >> 3) * 1024u + (uint32_t)(ng & 7) * 128u;
    const uint32_t bgSw = (uint32_t)(ng & 7);
    const uint32_t bmBase = sbase + E_B3 + (uint32_t)(nm >> 3) * 1024u + (uint32_t)(nm & 7) * 128u;
    const uint32_t bmSw = (uint32_t)(nm & 7);

    const int grid = gridDim.x;
    const int bid = blockIdx.x;
    const int nloc = (ntiles - bid + grid - 1) / grid;
    const int gg = lane >> 2, tt = lane & 3;
    const int ttOdd = tt & 1;

    // staging lambdas (macros via code)
    // idx stage: threads 0..255
    #define STAGE_IDX(slot, tile)  do { \
        if (tid < 256) { \
            int which = tid >> 7, e = tid & 127; \
            long long eg = (long long)(tile) * TM + e; \
            int v = -1; \
            if (eg < (long long)E) { \
                long long pos = (long long)which * E + eg; \
                v = is64 ? (int)e64[pos] : e32[pos]; \
            } \
            sI[(slot) * 256 + tid] = v; \
            if (which && v >= 0) atomicAdd(&g_cnt[v], 1.0f); \
        } \
    } while (0)

    #define GATHER_A3(aoff, tile) do { \
        int eb_ = (tile) * TM; \
        _Pragma("unroll") \
        for (int idx = tid; idx < 2048; idx += BLK) { \
            int e = idx >> 4, k4 = (idx & 15) << 2; \
            long long eg = (long long)eb_ + e; \
            float4 x = make_float4(0.f, 0.f, 0.f, 0.f); \
            if (eg < (long long)E) x = *(const float4*)(edge_attr + eg * ED + k4); \
            __nv_bfloat162 p0 = __floats2bfloat162_rn(x.x, x.y); \
            __nv_bfloat162 p1 = __floats2bfloat162_rn(x.z, x.w); \
            uint2 u = make_uint2(*(uint32_t*)&p0, *(uint32_t*)&p1); \
            uint32_t off = (uint32_t)(e >> 3) * 1024u + (uint32_t)(e & 7) * 128u + (uint32_t)k4 * 2u; \
            *(uint2*)(sm + (aoff) + SW128(off)) = u; \
        } \
    } while (0)

    // prologue
    STAGE_IDX(0, bid);
    __syncthreads();
    GATHER_A3(E_A0, bid);
    if (nloc > 1) STAGE_IDX(1, bid + grid);
    __syncthreads();

    for (int L = 0; L < nloc; L++) {
        const int* sIL = sI + (L % 3) * 256;
        const uint32_t saAb = sbase + ((L & 1) ? E_A1 : E_A0);

        int dstA[2], dstB[2];
        #pragma unroll
        for (int i = 0; i < 2; i++) {
            int lr = 32 * rg + 16 * i + gg;
            dstA[i] = sIL[128 + lr];
            dstB[i] = sIL[128 + lr + 8];
        }

        // ---- a. PS stage: PS[e][c] = P1[src][c] + P2[dst][c] (bias inside P1) ----
        {
            int e = tid & 127;
            int c6 = tid >> 7;     // 0..5
            int src = sIL[e], dst = sIL[128 + e];
            if (src >= 0) {
                const uint4* p1 = (const uint4*)(g_P1 + (size_t)src * 192 + c6 * 32);
                const uint4* p2 = (const uint4*)(g_P2 + (size_t)dst * 192 + c6 * 32);
                float* psrow = PS + e * PS_STRIDE + c6 * 32;
                #pragma unroll
                for (int q = 0; q < 4; q++) {
                    uint4 w1 = p1[q], w2 = p2[q];
                    *(float2*)(psrow + q * 8 + 0) = bfadd2(w1.x, w2.x);
                    *(float2*)(psrow + q * 8 + 2) = bfadd2(w1.y, w2.y);
                    *(float2*)(psrow + q * 8 + 4) = bfadd2(w1.z, w2.z);
                    *(float2*)(psrow + q * 8 + 6) = bfadd2(w1.w, w2.w);
                }
            }
        }

        // ---- b. MMA: z3 = A3 @ B3, K=64 ----
        float cgx[2][2][4], cm[2][2][4];
        #pragma unroll
        for (int i = 0; i < 2; i++)
            #pragma unroll
            for (int j = 0; j < 2; j++)
                #pragma unroll
                for (int c = 0; c < 4; c++) { cgx[i][j][c] = 0.f; cm[i][j][c] = 0.f; }

        uint32_t aBase[2], aSw[2];
        #pragma unroll
        for (int i = 0; i < 2; i++) {
            int e = 32 * rg + 16 * i + a_erow;
            aBase[i] = saAb + (uint32_t)(e >> 3) * 1024u + (uint32_t)(e & 7) * 128u;
            aSw[i] = (uint32_t)(e & 7);
        }
        #pragma unroll
        for (int kc = 0; kc < 4; kc++) {
            uint32_t kc2 = (uint32_t)(kc << 1);
            uint32_t aF[2][4], bg[4], bm[4];
            #pragma unroll
            for (int i = 0; i < 2; i++)
                ldsm_x4(aF[i], aBase[i] + (((kc2 | (uint32_t)a_khalf) ^ aSw[i]) << 4));
            ldsm_x4(bg, bgBase + (((kc2 | (uint32_t)b_khalf) ^ bgSw) << 4));
            ldsm_x4(bm, bmBase + (((kc2 | (uint32_t)b_khalf) ^ bmSw) << 4));
            #pragma unroll
            for (int i = 0; i < 2; i++) {
                mma16816(cgx[i][0], aF[i], bg);
                mma16816(cgx[i][1], aF[i], bg + 2);
                mma16816(cm[i][0], aF[i], bm);
                mma16816(cm[i][1], aF[i], bm + 2);
            }
        }

        // ---- c. stage next tile ----
        if (L + 1 < nloc) {
            GATHER_A3((L & 1) ? E_A0 : E_A1, bid + (L + 1) * grid);
            if (L + 2 < nloc) STAGE_IDX((L + 2) % 3, bid + (L + 2) * grid);
        }

        __syncthreads();   // d. PS + next A3 committed

        // ---- e. epilogue ----
        #pragma unroll
        for (int i = 0; i < 2; i++) {
            int lr0 = 32 * rg + 16 * i + gg;
            int lr1 = lr0 + 8;
            int dst0 = dstA[i], dst1 = dstB[i];
            #pragma unroll
            for (int j = 0; j < 2; j++) {
                int c = ng0 + 8 * j + 2 * tt;
                float2 pg0 = *(float2*)(PS + lr0 * PS_STRIDE + c);
                float2 pm0 = *(float2*)(PS + lr0 * PS_STRIDE + c + ND);
                float2 pg1 = *(float2*)(PS + lr1 * PS_STRIDE + c);
                float2 pm1 = *(float2*)(PS + lr1 * PS_STRIDE + c + ND);
                float v00 = act_gm(cgx[i][j][0] + pg0.x, cm[i][j][0] + pm0.x);
                float v01 = act_gm(cgx[i][j][1] + pg0.y, cm[i][j][1] + pm0.y);
                float v10 = act_gm(cgx[i][j][2] + pg1.x, cm[i][j][2] + pm1.x);
                float v11 = act_gm(cgx[i][j][3] + pg1.y, cm[i][j][3] + pm1.y);
                float s0 = ttOdd ? v00 : v10;
                float s1 = ttOdd ? v01 : v11;
                float r0 = __shfl_xor_sync(0xffffffffu, s0, 1);
                float r1 = __shfl_xor_sync(0xffffffffu, s1, 1);
                int colbase = ng0 + 8 * j + (tt >> 1) * 4;
                if (!ttOdd) {
                    if (dst0 >= 0)
                        asm volatile("red.global.add.v4.f32 [%0], {%1,%2,%3,%4};"
                            :: "l"(out + (long long)dst0 * ND + colbase),
                               "f"(v00), "f"(v01), "f"(r0), "f"(r1) : "memory");
                } else {
                    if (dst1 >= 0)
                        asm volatile("red.global.add.v4.f32 [%0], {%1,%2,%3,%4};"
                            :: "l"(out + (long long)dst1 * ND + colbase),
                               "f"(r0), "f"(r1), "f"(v10), "f"(v11) : "memory");
                }
            }
        }

        __syncthreads();   // f. epilogue reads done; PS reusable
    }
    #undef STAGE_IDX
    #undef GATHER_A3
}

extern "C" void kernel_launch(void* const* d_in, const int* in_sizes, int n_in,
                              void* d_out, int out_size) {
    const float* h   = (const float*)d_in[0];
    const void*  ei  = d_in[1];
    const float* ea  = (const float*)d_in[2];
    const float* W_e = (const float*)d_in[3];
    const float* b_e = (const float*)d_in[4];
    const float* W_n = (const float*)d_in[5];
    const float* b_n = (const float*)d_in[6];
    float* out = (float*)d_out;

    int N = in_sizes[0] / ND;
    int E = in_sizes[2] / ED;
    long long total4 = (long long)N * ND / 4;
    long long nwords = (long long)in_sizes[1];

    int ib = (int)((total4 + 255) / 256);
    init_kernel<<<ib, 256>>>((float4*)out, (const uint32_t*)ei, total4, N, nwords);

    int nblocks = (N + 63) / 64;
    cudaFuncSetAttribute(node_kernel, cudaFuncAttributeMaxDynamicSharedMemorySize, N_SMEM);
    node_kernel<<<nblocks, ABLK, N_SMEM>>>(h, W_e, b_e, W_n, b_n, N);

    int ntiles = (E + TM - 1) / TM;
    cudaFuncSetAttribute(edge_kernel, cudaFuncAttributeMaxDynamicSharedMemorySize, E_SMEM);
    int grid = ntiles < 148 ? ntiles : 148;
    edge_kernel<<<grid, BLK, E_SMEM>>>(ei, ea, W_e, W_n, out, E, ntiles);

    finalize_kernel<<<ib, 256>>>((const float4*)h, (float4*)out, total4);
}

// round 8
// speedup vs baseline: 1.8286x; 1.2301x over previous
#include <cuda_runtime.h>
#include <cuda_bf16.h>
#include <stdint.h>
#include <math.h>

#define ND 96
#define ED 64
#define TM 128            // edges per tile
#define BLK 768           // edge kernel threads (24 warps)
#define ABLK 512          // node kernel threads
#define MAXN 65536

__device__ __nv_bfloat16 g_P1[(size_t)MAXN * 192];   // h*W_src + bias (gate|msg)
__device__ __nv_bfloat16 g_P2[(size_t)MAXN * 192];   // h*W_dst
__device__ float g_cnt[MAXN];
__device__ int g_is64;

// ---- edge kernel smem layout ----
#define E_B3  0           // 192x64 bf16 blocked SW128 (24576)
#define E_A0  24576       // A3 buf0: 128x64 bf16 (16384)
#define E_A1  40960       // A3 buf1 (16384)
#define E_PS1 57344       // PS1: 128 rows x 400B bf16 (51200)
#define E_PS2 108544      // PS2: 51200
#define E_SI  159744      // 3 x (src[128]|dst[128]) (3072)
#define E_SMEM 162816
#define PSROW 400

// ---- node kernel smem ----
#define N_B 0             // 384x96(k pad 128) bf16 blocked (98304)
#define N_A 98304         // 64x96(pad 128) bf16 (16384)
#define N_SMEM 114688

#define SW128(o) ((o) ^ (((o) >> 3) & 0x70))

__device__ __forceinline__ uint32_t smem_u32(const void* p) {
    uint32_t r;
    asm("{ .reg .u64 t; cvta.to.shared.u64 t, %1; cvt.u32.u64 %0, t; }"
        : "=r"(r) : "l"(p));
    return r;
}
__device__ __forceinline__ void ldsm_x4(uint32_t* r, uint32_t addr) {
    asm volatile("ldmatrix.sync.aligned.m8n8.x4.shared.b16 {%0,%1,%2,%3}, [%4];"
        : "=r"(r[0]), "=r"(r[1]), "=r"(r[2]), "=r"(r[3]) : "r"(addr));
}
__device__ __forceinline__ void mma16816(float* c, const uint32_t* a, const uint32_t* b) {
    asm volatile("mma.sync.aligned.m16n8k16.row.col.f32.bf16.bf16.f32 "
        "{%0,%1,%2,%3}, {%4,%5,%6,%7}, {%8,%9}, {%0,%1,%2,%3};"
        : "+f"(c[0]), "+f"(c[1]), "+f"(c[2]), "+f"(c[3])
        : "r"(a[0]), "r"(a[1]), "r"(a[2]), "r"(a[3]), "r"(b[0]), "r"(b[1]));
}
__device__ __forceinline__ float act_gm(float xg, float xn) {
    float t;
    asm("tanh.approx.f32 %0, %1;" : "=f"(t) : "f"(xg * 0.5f));
    float gate = fmaf(t, 0.5f, 0.5f);
    float p;
    asm("ex2.approx.f32 %0, %1;" : "=f"(p) : "f"(-fabsf(xn) * 1.4426950408889634f));
    float l;
    asm("lg2.approx.f32 %0, %1;" : "=f"(l) : "f"(1.0f + p));
    float sp = fmaxf(xn, 0.0f) + 0.69314718055994531f * l;
    return gate * sp;
}
__device__ __forceinline__ float2 lds_bf2f(const char* p) {
    __nv_bfloat162 v = *(const __nv_bfloat162*)p;
    return __bfloat1622float2(v);
}

// ---------------- init / finalize ----------------
__global__ void init_kernel(float4* __restrict__ out4, const uint32_t* __restrict__ ew,
                            long long total4, int n, long long nwords) {
    long long i = (long long)blockIdx.x * blockDim.x + threadIdx.x;
    if (i < total4) out4[i] = make_float4(0.f, 0.f, 0.f, 0.f);
    if (i < n) g_cnt[i] = 0.0f;
    if (i == 0) {
        int is64 = 1;
        long long m = nwords < 256 ? nwords : 256;
        for (long long w = 1; w < m; w += 2)
            if (ew[w] != 0u) { is64 = 0; break; }
        g_is64 = is64;
    }
}

__global__ void finalize_kernel(const float4* __restrict__ h4, float4* __restrict__ out4,
                                long long total4) {
    long long i = (long long)blockIdx.x * blockDim.x + threadIdx.x;
    if (i < total4) {
        int node = (int)(i / (ND / 4));
        float c = g_cnt[node];
        c = c < 1.0f ? 1.0f : c;
        float inv = 1.0f / c;
        float4 a = h4[i], b = out4[i];
        out4[i] = make_float4(a.x + b.x * inv, a.y + b.y * inv,
                              a.z + b.z * inv, a.w + b.w * inv);
    }
}

// ---------------- node precompute kernel ----------------
// P[node][384] = h[node][0:96] @ Wcat[96][384], cols: [P1 gate|P1 msg|P2 gate|P2 msg]
__global__ __launch_bounds__(ABLK, 1)
void node_kernel(const float* __restrict__ h,
                 const float* __restrict__ W_e, const float* __restrict__ b_e,
                 const float* __restrict__ W_n, const float* __restrict__ b_n, int N) {
    extern __shared__ char sm[];
    const uint32_t sbase = smem_u32(sm);
    const int tid = threadIdx.x;
    const int wid = tid >> 5, lane = tid & 31;
    const int rg = wid & 1, cg = wid >> 1;   // 2 row groups x 8 col groups (48 cols)
    const int na0 = blockIdx.x * 64;

    for (int idx = tid; idx < 384 * 64; idx += ABLK) {
        int n = idx >> 6, kp = idx & 63;
        if (kp < 48) {
            int k = kp * 2;
            float f0, f1;
            if (n < 96)       { f0 = W_e[k * 96 + n];             f1 = W_e[(k + 1) * 96 + n]; }
            else if (n < 192) { f0 = W_n[k * 96 + (n - 96)];      f1 = W_n[(k + 1) * 96 + (n - 96)]; }
            else if (n < 288) { f0 = W_e[(96 + k) * 96 + (n - 192)]; f1 = W_e[(97 + k) * 96 + (n - 192)]; }
            else              { f0 = W_n[(96 + k) * 96 + (n - 288)]; f1 = W_n[(97 + k) * 96 + (n - 288)]; }
            __nv_bfloat162 p = __floats2bfloat162_rn(f0, f1);
            uint32_t off = (uint32_t)(kp >> 5) * 49152u + (uint32_t)(n >> 3) * 1024u
                         + (uint32_t)(n & 7) * 128u + (uint32_t)(k & 63) * 2u;
            *(uint32_t*)(sm + N_B + SW128(off)) = *(uint32_t*)&p;
        }
    }
    for (int idx = tid; idx < 64 * 64; idx += ABLK) {
        int r = idx >> 6, kp = idx & 63;
        if (kp < 48) {
            int k = kp * 2, node = na0 + r;
            float f0 = 0.f, f1 = 0.f;
            if (node < N) { f0 = h[node * 96 + k]; f1 = h[node * 96 + k + 1]; }
            __nv_bfloat162 p = __floats2bfloat162_rn(f0, f1);
            uint32_t off = (uint32_t)(kp >> 5) * 8192u + (uint32_t)(r >> 3) * 1024u
                         + (uint32_t)(r & 7) * 128u + (uint32_t)(k & 63) * 2u;
            *(uint32_t*)(sm + N_A + SW128(off)) = *(uint32_t*)&p;
        }
    }
    __syncthreads();

    const int a_m = lane >> 3;
    const int a_erow = ((a_m & 1) << 3) + (lane & 7);
    const int a_khalf = a_m >> 1;
    const int b_nrow = ((a_m & 2) << 2) + (lane & 7);
    const int b_khalf = a_m & 1;

    uint32_t aBase[2], aSw[2];
    #pragma unroll
    for (int i = 0; i < 2; i++) {
        int e = 32 * rg + 16 * i + a_erow;
        aBase[i] = sbase + N_A + (uint32_t)(e >> 3) * 1024u + (uint32_t)(e & 7) * 128u;
        aSw[i] = (uint32_t)(e & 7);
    }
    uint32_t bBase[3], bSw[3];
    #pragma unroll
    for (int nb = 0; nb < 3; nb++) {
        int n = 48 * cg + 16 * nb + b_nrow;
        bBase[nb] = sbase + N_B + (uint32_t)(n >> 3) * 1024u + (uint32_t)(n & 7) * 128u;
        bSw[nb] = (uint32_t)(n & 7);
    }

    float acc[2][6][4];
    #pragma unroll
    for (int i = 0; i < 2; i++)
        #pragma unroll
        for (int b = 0; b < 6; b++)
            #pragma unroll
            for (int c = 0; c < 4; c++) acc[i][b][c] = 0.f;

    #pragma unroll
    for (int kc = 0; kc < 6; kc++) {
        uint32_t kblkA = (uint32_t)(kc >> 2) * 8192u;
        uint32_t kblkB = (uint32_t)(kc >> 2) * 49152u;
        uint32_t kc2 = (uint32_t)((kc & 3) << 1);
        uint32_t aF[2][4], bF[3][4];
        #pragma unroll
        for (int i = 0; i < 2; i++)
            ldsm_x4(aF[i], kblkA + aBase[i] + ((((kc2 | (uint32_t)a_khalf) ^ aSw[i])) << 4));
        #pragma unroll
        for (int nb = 0; nb < 3; nb++)
            ldsm_x4(bF[nb], kblkB + bBase[nb] + ((((kc2 | (uint32_t)b_khalf) ^ bSw[nb])) << 4));
        #pragma unroll
        for (int i = 0; i < 2; i++)
            #pragma unroll
            for (int nb = 0; nb < 3; nb++) {
                mma16816(acc[i][2 * nb], aF[i], bF[nb]);
                mma16816(acc[i][2 * nb + 1], aF[i], bF[nb] + 2);
            }
    }

    const int gg = lane >> 2, tt = lane & 3;
    #pragma unroll
    for (int i = 0; i < 2; i++) {
        int lr0 = 32 * rg + 16 * i + gg;
        int n0 = na0 + lr0, n1 = n0 + 8;
        #pragma unroll
        for (int b = 0; b < 6; b++) {
            int cn = 48 * cg + 8 * b + 2 * tt;
            float bias0 = 0.f, bias1 = 0.f;
            if (cn < 96)       { bias0 = b_e[cn];      bias1 = b_e[cn + 1]; }
            else if (cn < 192) { bias0 = b_n[cn - 96]; bias1 = b_n[cn - 95]; }
            __nv_bfloat16* arr = (cn < 192) ? g_P1 : g_P2;
            int cc = (cn < 192) ? cn : cn - 192;
            __nv_bfloat162 v0 = __floats2bfloat162_rn(acc[i][b][0] + bias0, acc[i][b][1] + bias1);
            __nv_bfloat162 v1 = __floats2bfloat162_rn(acc[i][b][2] + bias0, acc[i][b][3] + bias1);
            if (n0 < N) *(__nv_bfloat162*)(arr + (size_t)n0 * 192 + cc) = v0;
            if (n1 < N) *(__nv_bfloat162*)(arr + (size_t)n1 * 192 + cc) = v1;
        }
    }
}

// ---------------- edge kernel ----------------
__global__ __launch_bounds__(BLK, 1)
void edge_kernel(const void* __restrict__ eidx,
                 const float* __restrict__ edge_attr,
                 const float* __restrict__ W_e, const float* __restrict__ W_n,
                 float* __restrict__ out, int E, int ntiles) {
    extern __shared__ char sm[];
    const uint32_t sbase = smem_u32(sm);
    const int tid = threadIdx.x;
    const int wid = tid >> 5, lane = tid & 31;
    const int rg = wid & 3;          // rows [32*rg, 32*rg+32)
    const int cg = wid >> 2;         // 0..5: gate cols [16cg,+16), msg +96

    // B3 = W3 (rows 192..255 of We/Wn), [n][k] bf16 blocked SW128
    for (int idx = tid; idx < 192 * 32; idx += BLK) {
        int n = idx >> 5;
        int k = (idx & 31) * 2;
        float f0, f1;
        if (n < 96) { f0 = W_e[(192 + k) * 96 + n];        f1 = W_e[(193 + k) * 96 + n]; }
        else        { f0 = W_n[(192 + k) * 96 + (n - 96)]; f1 = W_n[(193 + k) * 96 + (n - 96)]; }
        __nv_bfloat162 p = __floats2bfloat162_rn(f0, f1);
        uint32_t off = (uint32_t)(n >> 3) * 1024u + (uint32_t)(n & 7) * 128u + (uint32_t)k * 2u;
        *(uint32_t*)(sm + E_B3 + SW128(off)) = *(uint32_t*)&p;
    }

    const int is64 = g_is64;
    const long long* e64 = (const long long*)eidx;
    const int*       e32 = (const int*)eidx;
    int* sI = (int*)(sm + E_SI);

    const int a_m = lane >> 3;
    const int a_erow = ((a_m & 1) << 3) + (lane & 7);
    const int a_khalf = a_m >> 1;
    const int b_nrow = ((a_m & 2) << 2) + (lane & 7);
    const int b_khalf = a_m & 1;

    const int ng0 = 16 * cg;
    const int ng = ng0 + b_nrow;
    const int nm = ng + ND;
    const uint32_t bgBase = sbase + E_B3 + (uint32_t)(ng >> 3) * 1024u + (uint32_t)(ng & 7) * 128u;
    const uint32_t bgSw = (uint32_t)(ng & 7);
    const uint32_t bmBase = sbase + E_B3 + (uint32_t)(nm >> 3) * 1024u + (uint32_t)(nm & 7) * 128u;
    const uint32_t bmSw = (uint32_t)(nm & 7);

    const int grid = gridDim.x;
    const int bid = blockIdx.x;
    const int nloc = (ntiles - bid + grid - 1) / grid;
    const int gg = lane >> 2, tt = lane & 3;
    const int ttOdd = tt & 1;

    // PS chunk decomposition: 6144 chunks of 16B; thread t -> chunks t + 768*i
    // 768 = 32 * 24, so row advances by exactly 32 per step, col fixed.
    const int ps_r0 = tid / 24;
    const int ps_c  = tid - ps_r0 * 24;     // 0..23 (16B units within 384B row)

    #define STAGE_IDX(slot, tile)  do { \
        if (tid < 256) { \
            int which = tid >> 7, e = tid & 127; \
            long long eg = (long long)(tile) * TM + e; \
            int v = -1; \
            if (eg < (long long)E) { \
                long long pos = (long long)which * E + eg; \
                v = is64 ? (int)e64[pos] : e32[pos]; \
            } \
            sI[(slot) * 256 + tid] = v; \
            if (which && v >= 0) atomicAdd(&g_cnt[v], 1.0f); \
        } \
    } while (0)

    #define GATHER_A3(aoff, tile) do { \
        int eb_ = (tile) * TM; \
        _Pragma("unroll") \
        for (int idx = tid; idx < 2048; idx += BLK) { \
            int e = idx >> 4, k4 = (idx & 15) << 2; \
            long long eg = (long long)eb_ + e; \
            float4 x = make_float4(0.f, 0.f, 0.f, 0.f); \
            if (eg < (long long)E) x = *(const float4*)(edge_attr + eg * ED + k4); \
            __nv_bfloat162 p0 = __floats2bfloat162_rn(x.x, x.y); \
            __nv_bfloat162 p1 = __floats2bfloat162_rn(x.z, x.w); \
            uint2 u = make_uint2(*(uint32_t*)&p0, *(uint32_t*)&p1); \
            uint32_t off = (uint32_t)(e >> 3) * 1024u + (uint32_t)(e & 7) * 128u + (uint32_t)k4 * 2u; \
            *(uint2*)(sm + (aoff) + SW128(off)) = u; \
        } \
    } while (0)

    // prologue
    STAGE_IDX(0, bid);
    __syncthreads();
    GATHER_A3(E_A0, bid);
    if (nloc > 1) STAGE_IDX(1, bid + grid);
    __syncthreads();

    for (int L = 0; L < nloc; L++) {
        const int* sIL = sI + (L % 3) * 256;
        const uint32_t saAb = sbase + ((L & 1) ? E_A1 : E_A0);

        int dstA[2], dstB[2];
        #pragma unroll
        for (int i = 0; i < 2; i++) {
            int lr = 32 * rg + 16 * i + gg;
            dstA[i] = sIL[128 + lr];
            dstB[i] = sIL[128 + lr + 8];
        }

        // ---- a. PS stage via cp.async: PS1 <- P1[src], PS2 <- P2[dst] (bf16 raw) ----
        {
            #pragma unroll
            for (int i = 0; i < 8; i++) {
                int r = ps_r0 + 32 * i;         // 0..255
                int e = r >> 1;
                int arr = r & 1;
                int node = arr ? sIL[128 + e] : sIL[e];
                uint32_t sz = 16;
                if (node < 0) { node = 0; sz = 0; }
                const __nv_bfloat16* gsrc =
                    (arr ? g_P2 : g_P1) + (size_t)node * 192 + ps_c * 8;
                uint32_t sdst = sbase + (arr ? E_PS2 : E_PS1)
                              + (uint32_t)e * PSROW + (uint32_t)ps_c * 16;
                asm volatile("cp.async.cg.shared.global [%0], [%1], 16, %2;"
                             :: "r"(sdst), "l"(gsrc), "r"(sz));
            }
            asm volatile("cp.async.commit_group;" ::: "memory");
        }

        // ---- b. MMA: z3 = A3 @ B3, K=64 ----
        float cgx[2][2][4], cm[2][2][4];
        #pragma unroll
        for (int i = 0; i < 2; i++)
            #pragma unroll
            for (int j = 0; j < 2; j++)
                #pragma unroll
                for (int c = 0; c < 4; c++) { cgx[i][j][c] = 0.f; cm[i][j][c] = 0.f; }

        uint32_t aBase[2], aSw[2];
        #pragma unroll
        for (int i = 0; i < 2; i++) {
            int e = 32 * rg + 16 * i + a_erow;
            aBase[i] = saAb + (uint32_t)(e >> 3) * 1024u + (uint32_t)(e & 7) * 128u;
            aSw[i] = (uint32_t)(e & 7);
        }
        #pragma unroll
        for (int kc = 0; kc < 4; kc++) {
            uint32_t kc2 = (uint32_t)(kc << 1);
            uint32_t aF[2][4], bg[4], bm[4];
            #pragma unroll
            for (int i = 0; i < 2; i++)
                ldsm_x4(aF[i], aBase[i] + (((kc2 | (uint32_t)a_khalf) ^ aSw[i]) << 4));
            ldsm_x4(bg, bgBase + (((kc2 | (uint32_t)b_khalf) ^ bgSw) << 4));
            ldsm_x4(bm, bmBase + (((kc2 | (uint32_t)b_khalf) ^ bmSw) << 4));
            #pragma unroll
            for (int i = 0; i < 2; i++) {
                mma16816(cgx[i][0], aF[i], bg);
                mma16816(cgx[i][1], aF[i], bg + 2);
                mma16816(cm[i][0], aF[i], bm);
                mma16816(cm[i][1], aF[i], bm + 2);
            }
        }

        // ---- c. stage next tile ----
        if (L + 1 < nloc) {
            GATHER_A3((L & 1) ? E_A0 : E_A1, bid + (L + 1) * grid);
            if (L + 2 < nloc) STAGE_IDX((L + 2) % 3, bid + (L + 2) * grid);
        }

        asm volatile("cp.async.wait_group 0;" ::: "memory");
        __syncthreads();   // d. PS + next A3 committed

        // ---- e. epilogue: z = acc + PS1 + PS2; act; butterfly v4 RED ----
        #pragma unroll
        for (int i = 0; i < 2; i++) {
            int lr0 = 32 * rg + 16 * i + gg;
            int lr1 = lr0 + 8;
            int dst0 = dstA[i], dst1 = dstB[i];
            const char* r0p = sm + E_PS1 + lr0 * PSROW;
            const char* r1p = sm + E_PS1 + lr1 * PSROW;
            const char* q0p = sm + E_PS2 + lr0 * PSROW;
            const char* q1p = sm + E_PS2 + lr1 * PSROW;
            #pragma unroll
            for (int j = 0; j < 2; j++) {
                int c = ng0 + 8 * j + 2 * tt;
                float2 g10 = lds_bf2f(r0p + 2 * c);
                float2 m10 = lds_bf2f(r0p + 2 * c + 192);
                float2 g20 = lds_bf2f(q0p + 2 * c);
                float2 m20 = lds_bf2f(q0p + 2 * c + 192);
                float2 g11 = lds_bf2f(r1p + 2 * c);
                float2 m11 = lds_bf2f(r1p + 2 * c + 192);
                float2 g21 = lds_bf2f(q1p + 2 * c);
                float2 m21 = lds_bf2f(q1p + 2 * c + 192);
                float v00 = act_gm(cgx[i][j][0] + g10.x + g20.x, cm[i][j][0] + m10.x + m20.x);
                float v01 = act_gm(cgx[i][j][1] + g10.y + g20.y, cm[i][j][1] + m10.y + m20.y);
                float v10 = act_gm(cgx[i][j][2] + g11.x + g21.x, cm[i][j][2] + m11.x + m21.x);
                float v11 = act_gm(cgx[i][j][3] + g11.y + g21.y, cm[i][j][3] + m11.y + m21.y);
                float s0 = ttOdd ? v00 : v10;
                float s1 = ttOdd ? v01 : v11;
                float r0 = __shfl_xor_sync(0xffffffffu, s0, 1);
                float r1 = __shfl_xor_sync(0xffffffffu, s1, 1);
                int colbase = ng0 + 8 * j + (tt >> 1) * 4;
                if (!ttOdd) {
                    if (dst0 >= 0)
                        asm volatile("red.global.add.v4.f32 [%0], {%1,%2,%3,%4};"
                            :: "l"(out + (long long)dst0 * ND + colbase),
                               "f"(v00), "f"(v01), "f"(r0), "f"(r1) : "memory");
                } else {
                    if (dst1 >= 0)
                        asm volatile("red.global.add.v4.f32 [%0], {%1,%2,%3,%4};"
                            :: "l"(out + (long long)dst1 * ND + colbase),
                               "f"(r0), "f"(r1), "f"(v10), "f"(v11) : "memory");
                }
            }
        }

        __syncthreads();   // f. epilogue reads done; PS reusable
    }
    #undef STAGE_IDX
    #undef GATHER_A3
}

extern "C" void kernel_launch(void* const* d_in, const int* in_sizes, int n_in,
                              void* d_out, int out_size) {
    const float* h   = (const float*)d_in[0];
    const void*  ei  = d_in[1];
    const float* ea  = (const float*)d_in[2];
    const float* W_e = (const float*)d_in[3];
    const float* b_e = (const float*)d_in[4];
    const float* W_n = (const float*)d_in[5];
    const float* b_n = (const float*)d_in[6];
    float* out = (float*)d_out;

    int N = in_sizes[0] / ND;
    int E = in_sizes[2] / ED;
    long long total4 = (long long)N * ND / 4;
    long long nwords = (long long)in_sizes[1];

    int ib = (int)((total4 + 255) / 256);
    init_kernel<<<ib, 256>>>((float4*)out, (const uint32_t*)ei, total4, N, nwords);

    int nblocks = (N + 63) / 64;
    cudaFuncSetAttribute(node_kernel, cudaFuncAttributeMaxDynamicSharedMemorySize, N_SMEM);
    node_kernel<<<nblocks, ABLK, N_SMEM>>>(h, W_e, b_e, W_n, b_n, N);

    int ntiles = (E + TM - 1) / TM;
    cudaFuncSetAttribute(edge_kernel, cudaFuncAttributeMaxDynamicSharedMemorySize, E_SMEM);
    int grid = ntiles < 148 ? ntiles : 148;
    edge_kernel<<<grid, BLK, E_SMEM>>>(ei, ea, W_e, W_n, out, E, ntiles);

    finalize_kernel<<<ib, 256>>>((const float4*)h, (float4*)out, total4);
}

// round 9
// speedup vs baseline: 1.9633x; 1.0737x over previous
#include <cuda_runtime.h>
#include <cuda_bf16.h>
#include <stdint.h>
#include <math.h>

#define ND 96
#define ED 64
#define TM 128            // edges per tile
#define BLK 768           // edge kernel threads (24 warps)
#define ABLK 512          // node kernel threads
#define MAXN 65536

__device__ __nv_bfloat16 g_P1[(size_t)MAXN * 192];   // h*W_src + bias (gate|msg)
__device__ __nv_bfloat16 g_P2[(size_t)MAXN * 192];   // h*W_dst
__device__ float g_cnt[MAXN];
__device__ int g_is64;

// ---- edge kernel smem layout ----
#define E_B3  0           // 192x64 bf16 blocked SW128 (24576)
#define E_A0  24576       // A3 buf0: 128x64 bf16 (16384)
#define E_A1  40960       // A3 buf1 (16384)
#define E_PS0 57344       // PS buf0: 128 rows x 400B bf16 (51200)
#define E_PS1 108544      // PS buf1: 51200
#define E_SI  159744      // 3 x (src[128]|dst[128]) (3072)
#define E_SMEM 162816
#define PSROW 400

// ---- node kernel smem ----
#define N_B 0             // 384x96(k pad 128) bf16 blocked (98304)
#define N_A 98304         // 64x96(pad 128) bf16 (16384)
#define N_SMEM 114688

#define SW128(o) ((o) ^ (((o) >> 3) & 0x70))

__device__ __forceinline__ uint32_t smem_u32(const void* p) {
    uint32_t r;
    asm("{ .reg .u64 t; cvta.to.shared.u64 t, %1; cvt.u32.u64 %0, t; }"
        : "=r"(r) : "l"(p));
    return r;
}
__device__ __forceinline__ void ldsm_x4(uint32_t* r, uint32_t addr) {
    asm volatile("ldmatrix.sync.aligned.m8n8.x4.shared.b16 {%0,%1,%2,%3}, [%4];"
        : "=r"(r[0]), "=r"(r[1]), "=r"(r[2]), "=r"(r[3]) : "r"(addr));
}
__device__ __forceinline__ void mma16816(float* c, const uint32_t* a, const uint32_t* b) {
    asm volatile("mma.sync.aligned.m16n8k16.row.col.f32.bf16.bf16.f32 "
        "{%0,%1,%2,%3}, {%4,%5,%6,%7}, {%8,%9}, {%0,%1,%2,%3};"
        : "+f"(c[0]), "+f"(c[1]), "+f"(c[2]), "+f"(c[3])
        : "r"(a[0]), "r"(a[1]), "r"(a[2]), "r"(a[3]), "r"(b[0]), "r"(b[1]));
}
__device__ __forceinline__ float act_gm(float xg, float xn) {
    float t;
    asm("tanh.approx.f32 %0, %1;" : "=f"(t) : "f"(xg * 0.5f));
    float gate = fmaf(t, 0.5f, 0.5f);
    float p;
    asm("ex2.approx.f32 %0, %1;" : "=f"(p) : "f"(-fabsf(xn) * 1.4426950408889634f));
    float l;
    asm("lg2.approx.f32 %0, %1;" : "=f"(l) : "f"(1.0f + p));
    float sp = fmaxf(xn, 0.0f) + 0.69314718055994531f * l;
    return gate * sp;
}
__device__ __forceinline__ float2 lds_bf2f(const char* p) {
    __nv_bfloat162 v = *(const __nv_bfloat162*)p;
    return __bfloat1622float2(v);
}
__device__ __forceinline__ uint32_t hadd2u(uint32_t a, uint32_t b) {
    __nv_bfloat162 r = __hadd2(*(__nv_bfloat162*)&a, *(__nv_bfloat162*)&b);
    return *(uint32_t*)&r;
}

// ---------------- init / finalize ----------------
__global__ void init_kernel(float4* __restrict__ out4, const uint32_t* __restrict__ ew,
                            long long total4, int n, long long nwords) {
    long long i = (long long)blockIdx.x * blockDim.x + threadIdx.x;
    if (i < total4) out4[i] = make_float4(0.f, 0.f, 0.f, 0.f);
    if (i < n) g_cnt[i] = 0.0f;
    if (i == 0) {
        int is64 = 1;
        long long m = nwords < 256 ? nwords : 256;
        for (long long w = 1; w < m; w += 2)
            if (ew[w] != 0u) { is64 = 0; break; }
        g_is64 = is64;
    }
}

__global__ void finalize_kernel(const float4* __restrict__ h4, float4* __restrict__ out4,
                                long long total4) {
    long long i = (long long)blockIdx.x * blockDim.x + threadIdx.x;
    if (i < total4) {
        int node = (int)(i / (ND / 4));
        float c = g_cnt[node];
        c = c < 1.0f ? 1.0f : c;
        float inv = 1.0f / c;
        float4 a = h4[i], b = out4[i];
        out4[i] = make_float4(a.x + b.x * inv, a.y + b.y * inv,
                              a.z + b.z * inv, a.w + b.w * inv);
    }
}

// ---------------- node precompute kernel ----------------
// P[node][384] = h[node][0:96] @ Wcat[96][384], cols: [P1 gate|P1 msg|P2 gate|P2 msg]
__global__ __launch_bounds__(ABLK, 1)
void node_kernel(const float* __restrict__ h,
                 const float* __restrict__ W_e, const float* __restrict__ b_e,
                 const float* __restrict__ W_n, const float* __restrict__ b_n, int N) {
    extern __shared__ char sm[];
    const uint32_t sbase = smem_u32(sm);
    const int tid = threadIdx.x;
    const int wid = tid >> 5, lane = tid & 31;
    const int rg = wid & 1, cg = wid >> 1;   // 2 row groups x 8 col groups (48 cols)
    const int na0 = blockIdx.x * 64;

    for (int idx = tid; idx < 384 * 64; idx += ABLK) {
        int n = idx >> 6, kp = idx & 63;
        if (kp < 48) {
            int k = kp * 2;
            float f0, f1;
            if (n < 96)       { f0 = W_e[k * 96 + n];             f1 = W_e[(k + 1) * 96 + n]; }
            else if (n < 192) { f0 = W_n[k * 96 + (n - 96)];      f1 = W_n[(k + 1) * 96 + (n - 96)]; }
            else if (n < 288) { f0 = W_e[(96 + k) * 96 + (n - 192)]; f1 = W_e[(97 + k) * 96 + (n - 192)]; }
            else              { f0 = W_n[(96 + k) * 96 + (n - 288)]; f1 = W_n[(97 + k) * 96 + (n - 288)]; }
            __nv_bfloat162 p = __floats2bfloat162_rn(f0, f1);
            uint32_t off = (uint32_t)(kp >> 5) * 49152u + (uint32_t)(n >> 3) * 1024u
                         + (uint32_t)(n & 7) * 128u + (uint32_t)(k & 63) * 2u;
            *(uint32_t*)(sm + N_B + SW128(off)) = *(uint32_t*)&p;
        }
    }
    for (int idx = tid; idx < 64 * 64; idx += ABLK) {
        int r = idx >> 6, kp = idx & 63;
        if (kp < 48) {
            int k = kp * 2, node = na0 + r;
            float f0 = 0.f, f1 = 0.f;
            if (node < N) { f0 = h[node * 96 + k]; f1 = h[node * 96 + k + 1]; }
            __nv_bfloat162 p = __floats2bfloat162_rn(f0, f1);
            uint32_t off = (uint32_t)(kp >> 5) * 8192u + (uint32_t)(r >> 3) * 1024u
                         + (uint32_t)(r & 7) * 128u + (uint32_t)(k & 63) * 2u;
            *(uint32_t*)(sm + N_A + SW128(off)) = *(uint32_t*)&p;
        }
    }
    __syncthreads();

    const int a_m = lane >> 3;
    const int a_erow = ((a_m & 1) << 3) + (lane & 7);
    const int a_khalf = a_m >> 1;
    const int b_nrow = ((a_m & 2) << 2) + (lane & 7);
    const int b_khalf = a_m & 1;

    uint32_t aBase[2], aSw[2];
    #pragma unroll
    for (int i = 0; i < 2; i++) {
        int e = 32 * rg + 16 * i + a_erow;
        aBase[i] = sbase + N_A + (uint32_t)(e >> 3) * 1024u + (uint32_t)(e & 7) * 128u;
        aSw[i] = (uint32_t)(e & 7);
    }
    uint32_t bBase[3], bSw[3];
    #pragma unroll
    for (int nb = 0; nb < 3; nb++) {
        int n = 48 * cg + 16 * nb + b_nrow;
        bBase[nb] = sbase + N_B + (uint32_t)(n >> 3) * 1024u + (uint32_t)(n & 7) * 128u;
        bSw[nb] = (uint32_t)(n & 7);
    }

    float acc[2][6][4];
    #pragma unroll
    for (int i = 0; i < 2; i++)
        #pragma unroll
        for (int b = 0; b < 6; b++)
            #pragma unroll
            for (int c = 0; c < 4; c++) acc[i][b][c] = 0.f;

    #pragma unroll
    for (int kc = 0; kc < 6; kc++) {
        uint32_t kblkA = (uint32_t)(kc >> 2) * 8192u;
        uint32_t kblkB = (uint32_t)(kc >> 2) * 49152u;
        uint32_t kc2 = (uint32_t)((kc & 3) << 1);
        uint32_t aF[2][4], bF[3][4];
        #pragma unroll
        for (int i = 0; i < 2; i++)
            ldsm_x4(aF[i], kblkA + aBase[i] + ((((kc2 | (uint32_t)a_khalf) ^ aSw[i])) << 4));
        #pragma unroll
        for (int nb = 0; nb < 3; nb++)
            ldsm_x4(bF[nb], kblkB + bBase[nb] + ((((kc2 | (uint32_t)b_khalf) ^ bSw[nb])) << 4));
        #pragma unroll
        for (int i = 0; i < 2; i++)
            #pragma unroll
            for (int nb = 0; nb < 3; nb++) {
                mma16816(acc[i][2 * nb], aF[i], bF[nb]);
                mma16816(acc[i][2 * nb + 1], aF[i], bF[nb] + 2);
            }
    }

    const int gg = lane >> 2, tt = lane & 3;
    #pragma unroll
    for (int i = 0; i < 2; i++) {
        int lr0 = 32 * rg + 16 * i + gg;
        int n0 = na0 + lr0, n1 = n0 + 8;
        #pragma unroll
        for (int b = 0; b < 6; b++) {
            int cn = 48 * cg + 8 * b + 2 * tt;
            float bias0 = 0.f, bias1 = 0.f;
            if (cn < 96)       { bias0 = b_e[cn];      bias1 = b_e[cn + 1]; }
            else if (cn < 192) { bias0 = b_n[cn - 96]; bias1 = b_n[cn - 95]; }
            __nv_bfloat16* arr = (cn < 192) ? g_P1 : g_P2;
            int cc = (cn < 192) ? cn : cn - 192;
            __nv_bfloat162 v0 = __floats2bfloat162_rn(acc[i][b][0] + bias0, acc[i][b][1] + bias1);
            __nv_bfloat162 v1 = __floats2bfloat162_rn(acc[i][b][2] + bias0, acc[i][b][3] + bias1);
            if (n0 < N) *(__nv_bfloat162*)(arr + (size_t)n0 * 192 + cc) = v0;
            if (n1 < N) *(__nv_bfloat162*)(arr + (size_t)n1 * 192 + cc) = v1;
        }
    }
}

// ---------------- edge kernel ----------------
__global__ __launch_bounds__(BLK, 1)
void edge_kernel(const void* __restrict__ eidx,
                 const float* __restrict__ edge_attr,
                 const float* __restrict__ W_e, const float* __restrict__ W_n,
                 float* __restrict__ out, int E, int ntiles) {
    extern __shared__ char sm[];
    const uint32_t sbase = smem_u32(sm);
    const int tid = threadIdx.x;
    const int wid = tid >> 5, lane = tid & 31;
    const int rg = wid & 3;          // rows [32*rg, 32*rg+32)
    const int cg = wid >> 2;         // 0..5: gate cols [16cg,+16), msg +96

    // B3 = W3 (rows 192..255 of We/Wn), [n][k] bf16 blocked SW128
    for (int idx = tid; idx < 192 * 32; idx += BLK) {
        int n = idx >> 5;
        int k = (idx & 31) * 2;
        float f0, f1;
        if (n < 96) { f0 = W_e[(192 + k) * 96 + n];        f1 = W_e[(193 + k) * 96 + n]; }
        else        { f0 = W_n[(192 + k) * 96 + (n - 96)]; f1 = W_n[(193 + k) * 96 + (n - 96)]; }
        __nv_bfloat162 p = __floats2bfloat162_rn(f0, f1);
        uint32_t off = (uint32_t)(n >> 3) * 1024u + (uint32_t)(n & 7) * 128u + (uint32_t)k * 2u;
        *(uint32_t*)(sm + E_B3 + SW128(off)) = *(uint32_t*)&p;
    }

    const int is64 = g_is64;
    const long long* e64 = (const long long*)eidx;
    const int*       e32 = (const int*)eidx;
    int* sI = (int*)(sm + E_SI);

    const int a_m = lane >> 3;
    const int a_erow = ((a_m & 1) << 3) + (lane & 7);
    const int a_khalf = a_m >> 1;
    const int b_nrow = ((a_m & 2) << 2) + (lane & 7);
    const int b_khalf = a_m & 1;

    const int ng0 = 16 * cg;
    const int ng = ng0 + b_nrow;
    const int nm = ng + ND;
    const uint32_t bgBase = sbase + E_B3 + (uint32_t)(ng >> 3) * 1024u + (uint32_t)(ng & 7) * 128u;
    const uint32_t bgSw = (uint32_t)(ng & 7);
    const uint32_t bmBase = sbase + E_B3 + (uint32_t)(nm >> 3) * 1024u + (uint32_t)(nm & 7) * 128u;
    const uint32_t bmSw = (uint32_t)(nm & 7);

    const int grid = gridDim.x;
    const int bid = blockIdx.x;
    const int nloc = (ntiles - bid + grid - 1) / grid;
    const int gg = lane >> 2, tt = lane & 3;
    const int ttOdd = tt & 1;

    // PS chunk decomposition: 128 edges x 24 chunks of 16B; thread t -> (e0 = t/24, c = t%24),
    // e advances by 32 per step (768 = 32*24): 4 steps cover 128 edges.
    const int ps_e0 = tid / 24;
    const int ps_c  = tid - ps_e0 * 24;     // 0..23 (16B units within 384B row)

    #define STAGE_IDX(slot, tile)  do { \
        if (tid < 256) { \
            int which = tid >> 7, e = tid & 127; \
            long long eg = (long long)(tile) * TM + e; \
            int v = -1; \
            if (eg < (long long)E) { \
                long long pos = (long long)which * E + eg; \
                v = is64 ? (int)e64[pos] : e32[pos]; \
            } \
            sI[(slot) * 256 + tid] = v; \
            if (which && v >= 0) atomicAdd(&g_cnt[v], 1.0f); \
        } \
    } while (0)

    #define GATHER_A3(aoff, tile) do { \
        int eb_ = (tile) * TM; \
        _Pragma("unroll") \
        for (int idx = tid; idx < 2048; idx += BLK) { \
            int e = idx >> 4, k4 = (idx & 15) << 2; \
            long long eg = (long long)eb_ + e; \
            float4 x = make_float4(0.f, 0.f, 0.f, 0.f); \
            if (eg < (long long)E) x = *(const float4*)(edge_attr + eg * ED + k4); \
            __nv_bfloat162 p0 = __floats2bfloat162_rn(x.x, x.y); \
            __nv_bfloat162 p1 = __floats2bfloat162_rn(x.z, x.w); \
            uint2 u = make_uint2(*(uint32_t*)&p0, *(uint32_t*)&p1); \
            uint32_t off = (uint32_t)(e >> 3) * 1024u + (uint32_t)(e & 7) * 128u + (uint32_t)k4 * 2u; \
            *(uint2*)(sm + (aoff) + SW128(off)) = u; \
        } \
    } while (0)

    // prologue
    STAGE_IDX(0, bid);
    __syncthreads();
    GATHER_A3(E_A0, bid);
    if (nloc > 1) STAGE_IDX(1, bid + grid);
    __syncthreads();

    for (int L = 0; L < nloc; L++) {
        const int* sIL = sI + (L % 3) * 256;
        const uint32_t saAb = sbase + ((L & 1) ? E_A1 : E_A0);
        char* psb = sm + ((L & 1) ? E_PS1 : E_PS0);

        int dstA[2], dstB[2];
        #pragma unroll
        for (int i = 0; i < 2; i++) {
            int lr = 32 * rg + 16 * i + gg;
            dstA[i] = sIL[128 + lr];
            dstB[i] = sIL[128 + lr + 8];
        }

        // ---- a. PS stage: PS = P1[src] + P2[dst] (bf16 add), coalesced chunks ----
        {
            #pragma unroll
            for (int i = 0; i < 4; i++) {
                int e = ps_e0 + 32 * i;         // 0..127
                int src = sIL[e], dst = sIL[128 + e];
                if (src >= 0) {
                    uint4 a = *(const uint4*)(g_P1 + (size_t)src * 192 + ps_c * 8);
                    uint4 b = *(const uint4*)(g_P2 + (size_t)dst * 192 + ps_c * 8);
                    uint4 s;
                    s.x = hadd2u(a.x, b.x);
                    s.y = hadd2u(a.y, b.y);
                    s.z = hadd2u(a.z, b.z);
                    s.w = hadd2u(a.w, b.w);
                    *(uint4*)(psb + (uint32_t)e * PSROW + (uint32_t)ps_c * 16) = s;
                }
            }
        }

        // ---- b. MMA: z3 = A3 @ B3, K=64 ----
        float cgx[2][2][4], cm[2][2][4];
        #pragma unroll
        for (int i = 0; i < 2; i++)
            #pragma unroll
            for (int j = 0; j < 2; j++)
                #pragma unroll
                for (int c = 0; c < 4; c++) { cgx[i][j][c] = 0.f; cm[i][j][c] = 0.f; }

        uint32_t aBase[2], aSw[2];
        #pragma unroll
        for (int i = 0; i < 2; i++) {
            int e = 32 * rg + 16 * i + a_erow;
            aBase[i] = saAb + (uint32_t)(e >> 3) * 1024u + (uint32_t)(e & 7) * 128u;
            aSw[i] = (uint32_t)(e & 7);
        }
        #pragma unroll
        for (int kc = 0; kc < 4; kc++) {
            uint32_t kc2 = (uint32_t)(kc << 1);
            uint32_t aF[2][4], bg[4], bm[4];
            #pragma unroll
            for (int i = 0; i < 2; i++)
                ldsm_x4(aF[i], aBase[i] + (((kc2 | (uint32_t)a_khalf) ^ aSw[i]) << 4));
            ldsm_x4(bg, bgBase + (((kc2 | (uint32_t)b_khalf) ^ bgSw) << 4));
            ldsm_x4(bm, bmBase + (((kc2 | (uint32_t)b_khalf) ^ bmSw) << 4));
            #pragma unroll
            for (int i = 0; i < 2; i++) {
                mma16816(cgx[i][0], aF[i], bg);
                mma16816(cgx[i][1], aF[i], bg + 2);
                mma16816(cm[i][0], aF[i], bm);
                mma16816(cm[i][1], aF[i], bm + 2);
            }
        }

        // ---- c. stage next tile ----
        if (L + 1 < nloc) {
            GATHER_A3((L & 1) ? E_A0 : E_A1, bid + (L + 1) * grid);
            if (L + 2 < nloc) STAGE_IDX((L + 2) % 3, bid + (L + 2) * grid);
        }

        __syncthreads();   // d. single barrier: commits PS(L), A3(L+1), idx(L+2)

        // ---- e. epilogue: z = acc + PS; act; butterfly v4 RED ----
        #pragma unroll
        for (int i = 0; i < 2; i++) {
            int lr0 = 32 * rg + 16 * i + gg;
            int lr1 = lr0 + 8;
            int dst0 = dstA[i], dst1 = dstB[i];
            const char* r0p = psb + lr0 * PSROW;
            const char* r1p = psb + lr1 * PSROW;
            #pragma unroll
            for (int j = 0; j < 2; j++) {
                int c = ng0 + 8 * j + 2 * tt;
                float2 g0 = lds_bf2f(r0p + 2 * c);
                float2 m0 = lds_bf2f(r0p + 2 * c + 192);
                float2 g1 = lds_bf2f(r1p + 2 * c);
                float2 m1 = lds_bf2f(r1p + 2 * c + 192);
                float v00 = act_gm(cgx[i][j][0] + g0.x, cm[i][j][0] + m0.x);
                float v01 = act_gm(cgx[i][j][1] + g0.y, cm[i][j][1] + m0.y);
                float v10 = act_gm(cgx[i][j][2] + g1.x, cm[i][j][2] + m1.x);
                float v11 = act_gm(cgx[i][j][3] + g1.y, cm[i][j][3] + m1.y);
                float s0 = ttOdd ? v00 : v10;
                float s1 = ttOdd ? v01 : v11;
                float r0 = __shfl_xor_sync(0xffffffffu, s0, 1);
                float r1 = __shfl_xor_sync(0xffffffffu, s1, 1);
                int colbase = ng0 + 8 * j + (tt >> 1) * 4;
                if (!ttOdd) {
                    if (dst0 >= 0)
                        asm volatile("red.global.add.v4.f32 [%0], {%1,%2,%3,%4};"
                            :: "l"(out + (long long)dst0 * ND + colbase),
                               "f"(v00), "f"(v01), "f"(r0), "f"(r1) : "memory");
                } else {
                    if (dst1 >= 0)
                        asm volatile("red.global.add.v4.f32 [%0], {%1,%2,%3,%4};"
                            :: "l"(out + (long long)dst1 * ND + colbase),
                               "f"(r0), "f"(r1), "f"(v10), "f"(v11) : "memory");
                }
            }
        }
        // no trailing barrier: PS double-buffered, A3 write for L+2 is after
        // next iteration's barrier, dst indices already in registers.
    }
    #undef STAGE_IDX
    #undef GATHER_A3
}

extern "C" void kernel_launch(void* const* d_in, const int* in_sizes, int n_in,
                              void* d_out, int out_size) {
    const float* h   = (const float*)d_in[0];
    const void*  ei  = d_in[1];
    const float* ea  = (const float*)d_in[2];
    const float* W_e = (const float*)d_in[3];
    const float* b_e = (const float*)d_in[4];
    const float* W_n = (const float*)d_in[5];
    const float* b_n = (const float*)d_in[6];
    float* out = (float*)d_out;

    int N = in_sizes[0] / ND;
    int E = in_sizes[2] / ED;
    long long total4 = (long long)N * ND / 4;
    long long nwords = (long long)in_sizes[1];

    int ib = (int)((total4 + 255) / 256);
    init_kernel<<<ib, 256>>>((float4*)out, (const uint32_t*)ei, total4, N, nwords);

    int nblocks = (N + 63) / 64;
    cudaFuncSetAttribute(node_kernel, cudaFuncAttributeMaxDynamicSharedMemorySize, N_SMEM);
    node_kernel<<<nblocks, ABLK, N_SMEM>>>(h, W_e, b_e, W_n, b_n, N);

    int ntiles = (E + TM - 1) / TM;
    cudaFuncSetAttribute(edge_kernel, cudaFuncAttributeMaxDynamicSharedMemorySize, E_SMEM);
    int grid = ntiles < 148 ? ntiles : 148;
    edge_kernel<<<grid, BLK, E_SMEM>>>(ei, ea, W_e, W_n, out, E, ntiles);

    finalize_kernel<<<ib, 256>>>((const float4*)h, (float4*)out, total4);
}

// round 10
// speedup vs baseline: 2.0105x; 1.0240x over previous
#include <cuda_runtime.h>
#include <cuda_bf16.h>
#include <stdint.h>
#include <math.h>

#define ND 96
#define ED 64
#define TM 64             // edges per tile (per CTA)
#define BLK 384           // edge kernel threads (12 warps), 2 CTAs/SM
#define ABLK 512          // node kernel threads
#define MAXN 65536

__device__ __nv_bfloat16 g_P1[(size_t)MAXN * 192];   // h*W_src + bias (gate|msg)
__device__ __nv_bfloat16 g_P2[(size_t)MAXN * 192];   // h*W_dst
__device__ float g_cnt[MAXN];
__device__ int g_is64;

// ---- edge kernel smem layout (per CTA, 2 CTAs/SM) ----
#define E_B3  0           // 192x64 bf16 blocked SW128 (24576)
#define E_A0  24576       // A3 buf0: 64x64 bf16 (8192)
#define E_A1  32768       // A3 buf1 (8192)
#define E_PS0 40960       // PS buf0: 64 rows x 400B bf16 (25600)
#define E_PS1 66560       // PS buf1: 25600
#define E_SI  92160       // 3 x (src[64]|dst[64]) (1536)
#define E_SMEM 93696
#define PSROW 400

// ---- node kernel smem ----
#define N_B 0             // 384x96(k pad 128) bf16 blocked (98304)
#define N_A 98304         // 64x96(pad 128) bf16 (16384)
#define N_SMEM 114688

#define SW128(o) ((o) ^ (((o) >> 3) & 0x70))

__device__ __forceinline__ uint32_t smem_u32(const void* p) {
    uint32_t r;
    asm("{ .reg .u64 t; cvta.to.shared.u64 t, %1; cvt.u32.u64 %0, t; }"
        : "=r"(r) : "l"(p));
    return r;
}
__device__ __forceinline__ void ldsm_x4(uint32_t* r, uint32_t addr) {
    asm volatile("ldmatrix.sync.aligned.m8n8.x4.shared.b16 {%0,%1,%2,%3}, [%4];"
        : "=r"(r[0]), "=r"(r[1]), "=r"(r[2]), "=r"(r[3]) : "r"(addr));
}
__device__ __forceinline__ void mma16816(float* c, const uint32_t* a, const uint32_t* b) {
    asm volatile("mma.sync.aligned.m16n8k16.row.col.f32.bf16.bf16.f32 "
        "{%0,%1,%2,%3}, {%4,%5,%6,%7}, {%8,%9}, {%0,%1,%2,%3};"
        : "+f"(c[0]), "+f"(c[1]), "+f"(c[2]), "+f"(c[3])
        : "r"(a[0]), "r"(a[1]), "r"(a[2]), "r"(a[3]), "r"(b[0]), "r"(b[1]));
}
__device__ __forceinline__ float act_gm(float xg, float xn) {
    float t;
    asm("tanh.approx.f32 %0, %1;" : "=f"(t) : "f"(xg * 0.5f));
    float gate = fmaf(t, 0.5f, 0.5f);
    float p;
    asm("ex2.approx.f32 %0, %1;" : "=f"(p) : "f"(-fabsf(xn) * 1.4426950408889634f));
    float l;
    asm("lg2.approx.f32 %0, %1;" : "=f"(l) : "f"(1.0f + p));
    float sp = fmaxf(xn, 0.0f) + 0.69314718055994531f * l;
    return gate * sp;
}
__device__ __forceinline__ float2 lds_bf2f(const char* p) {
    __nv_bfloat162 v = *(const __nv_bfloat162*)p;
    return __bfloat1622float2(v);
}
__device__ __forceinline__ uint32_t hadd2u(uint32_t a, uint32_t b) {
    __nv_bfloat162 r = __hadd2(*(__nv_bfloat162*)&a, *(__nv_bfloat162*)&b);
    return *(uint32_t*)&r;
}

// ---------------- init / finalize ----------------
__global__ void init_kernel(float4* __restrict__ out4, const uint32_t* __restrict__ ew,
                            long long total4, int n, long long nwords) {
    long long i = (long long)blockIdx.x * blockDim.x + threadIdx.x;
    if (i < total4) out4[i] = make_float4(0.f, 0.f, 0.f, 0.f);
    if (i < n) g_cnt[i] = 0.0f;
    if (i == 0) {
        int is64 = 1;
        long long m = nwords < 256 ? nwords : 256;
        for (long long w = 1; w < m; w += 2)
            if (ew[w] != 0u) { is64 = 0; break; }
        g_is64 = is64;
    }
}

__global__ void finalize_kernel(const float4* __restrict__ h4, float4* __restrict__ out4,
                                long long total4) {
    long long i = (long long)blockIdx.x * blockDim.x + threadIdx.x;
    if (i < total4) {
        int node = (int)(i / (ND / 4));
        float c = g_cnt[node];
        c = c < 1.0f ? 1.0f : c;
        float inv = 1.0f / c;
        float4 a = h4[i], b = out4[i];
        out4[i] = make_float4(a.x + b.x * inv, a.y + b.y * inv,
                              a.z + b.z * inv, a.w + b.w * inv);
    }
}

// ---------------- node precompute kernel ----------------
// P[node][384] = h[node][0:96] @ Wcat[96][384], cols: [P1 gate|P1 msg|P2 gate|P2 msg]
__global__ __launch_bounds__(ABLK, 1)
void node_kernel(const float* __restrict__ h,
                 const float* __restrict__ W_e, const float* __restrict__ b_e,
                 const float* __restrict__ W_n, const float* __restrict__ b_n, int N) {
    extern __shared__ char sm[];
    const uint32_t sbase = smem_u32(sm);
    const int tid = threadIdx.x;
    const int wid = tid >> 5, lane = tid & 31;
    const int rg = wid & 1, cg = wid >> 1;   // 2 row groups x 8 col groups (48 cols)
    const int na0 = blockIdx.x * 64;

    for (int idx = tid; idx < 384 * 64; idx += ABLK) {
        int n = idx >> 6, kp = idx & 63;
        if (kp < 48) {
            int k = kp * 2;
            float f0, f1;
            if (n < 96)       { f0 = W_e[k * 96 + n];             f1 = W_e[(k + 1) * 96 + n]; }
            else if (n < 192) { f0 = W_n[k * 96 + (n - 96)];      f1 = W_n[(k + 1) * 96 + (n - 96)]; }
            else if (n < 288) { f0 = W_e[(96 + k) * 96 + (n - 192)]; f1 = W_e[(97 + k) * 96 + (n - 192)]; }
            else              { f0 = W_n[(96 + k) * 96 + (n - 288)]; f1 = W_n[(97 + k) * 96 + (n - 288)]; }
            __nv_bfloat162 p = __floats2bfloat162_rn(f0, f1);
            uint32_t off = (uint32_t)(kp >> 5) * 49152u + (uint32_t)(n >> 3) * 1024u
                         + (uint32_t)(n & 7) * 128u + (uint32_t)(k & 63) * 2u;
            *(uint32_t*)(sm + N_B + SW128(off)) = *(uint32_t*)&p;
        }
    }
    for (int idx = tid; idx < 64 * 64; idx += ABLK) {
        int r = idx >> 6, kp = idx & 63;
        if (kp < 48) {
            int k = kp * 2, node = na0 + r;
            float f0 = 0.f, f1 = 0.f;
            if (node < N) { f0 = h[node * 96 + k]; f1 = h[node * 96 + k + 1]; }
            __nv_bfloat162 p = __floats2bfloat162_rn(f0, f1);
            uint32_t off = (uint32_t)(kp >> 5) * 8192u + (uint32_t)(r >> 3) * 1024u
                         + (uint32_t)(r & 7) * 128u + (uint32_t)(k & 63) * 2u;
            *(uint32_t*)(sm + N_A + SW128(off)) = *(uint32_t*)&p;
        }
    }
    __syncthreads();

    const int a_m = lane >> 3;
    const int a_erow = ((a_m & 1) << 3) + (lane & 7);
    const int a_khalf = a_m >> 1;
    const int b_nrow = ((a_m & 2) << 2) + (lane & 7);
    const int b_khalf = a_m & 1;

    uint32_t aBase[2], aSw[2];
    #pragma unroll
    for (int i = 0; i < 2; i++) {
        int e = 32 * rg + 16 * i + a_erow;
        aBase[i] = sbase + N_A + (uint32_t)(e >> 3) * 1024u + (uint32_t)(e & 7) * 128u;
        aSw[i] = (uint32_t)(e & 7);
    }
    uint32_t bBase[3], bSw[3];
    #pragma unroll
    for (int nb = 0; nb < 3; nb++) {
        int n = 48 * cg + 16 * nb + b_nrow;
        bBase[nb] = sbase + N_B + (uint32_t)(n >> 3) * 1024u + (uint32_t)(n & 7) * 128u;
        bSw[nb] = (uint32_t)(n & 7);
    }

    float acc[2][6][4];
    #pragma unroll
    for (int i = 0; i < 2; i++)
        #pragma unroll
        for (int b = 0; b < 6; b++)
            #pragma unroll
            for (int c = 0; c < 4; c++) acc[i][b][c] = 0.f;

    #pragma unroll
    for (int kc = 0; kc < 6; kc++) {
        uint32_t kblkA = (uint32_t)(kc >> 2) * 8192u;
        uint32_t kblkB = (uint32_t)(kc >> 2) * 49152u;
        uint32_t kc2 = (uint32_t)((kc & 3) << 1);
        uint32_t aF[2][4], bF[3][4];
        #pragma unroll
        for (int i = 0; i < 2; i++)
            ldsm_x4(aF[i], kblkA + aBase[i] + ((((kc2 | (uint32_t)a_khalf) ^ aSw[i])) << 4));
        #pragma unroll
        for (int nb = 0; nb < 3; nb++)
            ldsm_x4(bF[nb], kblkB + bBase[nb] + ((((kc2 | (uint32_t)b_khalf) ^ bSw[nb])) << 4));
        #pragma unroll
        for (int i = 0; i < 2; i++)
            #pragma unroll
            for (int nb = 0; nb < 3; nb++) {
                mma16816(acc[i][2 * nb], aF[i], bF[nb]);
                mma16816(acc[i][2 * nb + 1], aF[i], bF[nb] + 2);
            }
    }

    const int gg = lane >> 2, tt = lane & 3;
    #pragma unroll
    for (int i = 0; i < 2; i++) {
        int lr0 = 32 * rg + 16 * i + gg;
        int n0 = na0 + lr0, n1 = n0 + 8;
        #pragma unroll
        for (int b = 0; b < 6; b++) {
            int cn = 48 * cg + 8 * b + 2 * tt;
            float bias0 = 0.f, bias1 = 0.f;
            if (cn < 96)       { bias0 = b_e[cn];      bias1 = b_e[cn + 1]; }
            else if (cn < 192) { bias0 = b_n[cn - 96]; bias1 = b_n[cn - 95]; }
            __nv_bfloat16* arr = (cn < 192) ? g_P1 : g_P2;
            int cc = (cn < 192) ? cn : cn - 192;
            __nv_bfloat162 v0 = __floats2bfloat162_rn(acc[i][b][0] + bias0, acc[i][b][1] + bias1);
            __nv_bfloat162 v1 = __floats2bfloat162_rn(acc[i][b][2] + bias0, acc[i][b][3] + bias1);
            if (n0 < N) *(__nv_bfloat162*)(arr + (size_t)n0 * 192 + cc) = v0;
            if (n1 < N) *(__nv_bfloat162*)(arr + (size_t)n1 * 192 + cc) = v1;
        }
    }
}

// ---------------- edge kernel (2 CTAs/SM) ----------------
__global__ __launch_bounds__(BLK, 2)
void edge_kernel(const void* __restrict__ eidx,
                 const float* __restrict__ edge_attr,
                 const float* __restrict__ W_e, const float* __restrict__ W_n,
                 float* __restrict__ out, int E, int ntiles) {
    extern __shared__ char sm[];
    const uint32_t sbase = smem_u32(sm);
    const int tid = threadIdx.x;
    const int wid = tid >> 5, lane = tid & 31;
    const int rg = wid & 1;          // rows [32*rg, 32*rg+32)
    const int cg = wid >> 1;         // 0..5: gate cols [16cg,+16), msg +96

    // B3 = W3 (rows 192..255 of We/Wn), [n][k] bf16 blocked SW128
    for (int idx = tid; idx < 192 * 32; idx += BLK) {
        int n = idx >> 5;
        int k = (idx & 31) * 2;
        float f0, f1;
        if (n < 96) { f0 = W_e[(192 + k) * 96 + n];        f1 = W_e[(193 + k) * 96 + n]; }
        else        { f0 = W_n[(192 + k) * 96 + (n - 96)]; f1 = W_n[(193 + k) * 96 + (n - 96)]; }
        __nv_bfloat162 p = __floats2bfloat162_rn(f0, f1);
        uint32_t off = (uint32_t)(n >> 3) * 1024u + (uint32_t)(n & 7) * 128u + (uint32_t)k * 2u;
        *(uint32_t*)(sm + E_B3 + SW128(off)) = *(uint32_t*)&p;
    }

    const int is64 = g_is64;
    const long long* e64 = (const long long*)eidx;
    const int*       e32 = (const int*)eidx;
    int* sI = (int*)(sm + E_SI);     // 3 slots x 128 ints (src[64]|dst[64])

    const int a_m = lane >> 3;
    const int a_erow = ((a_m & 1) << 3) + (lane & 7);
    const int a_khalf = a_m >> 1;
    const int b_nrow = ((a_m & 2) << 2) + (lane & 7);
    const int b_khalf = a_m & 1;

    const int ng0 = 16 * cg;
    const int ng = ng0 + b_nrow;
    const int nm = ng + ND;
    const uint32_t bgBase = sbase + E_B3 + (uint32_t)(ng >> 3) * 1024u + (uint32_t)(ng & 7) * 128u;
    const uint32_t bgSw = (uint32_t)(ng & 7);
    const uint32_t bmBase = sbase + E_B3 + (uint32_t)(nm >> 3) * 1024u + (uint32_t)(nm & 7) * 128u;
    const uint32_t bmSw = (uint32_t)(nm & 7);

    const int grid = gridDim.x;
    const int bid = blockIdx.x;
    const int nloc = (ntiles - bid + grid - 1) / grid;
    const int gg = lane >> 2, tt = lane & 3;
    const int ttOdd = tt & 1;

    // PS chunk decomposition: 64 edges x 24 chunks of 16B = 1536 chunks;
    // thread t -> (e0 = t/24, c = t%24), e advances by 16 per step (384 = 16*24).
    const int ps_e0 = tid / 24;
    const int ps_c  = tid - ps_e0 * 24;     // 0..23

    #define STAGE_IDX(slot, tile)  do { \
        if (tid < 2 * TM) { \
            int which = tid >> 6, e = tid & 63; \
            long long eg = (long long)(tile) * TM + e; \
            int v = -1; \
            if (eg < (long long)E) { \
                long long pos = (long long)which * E + eg; \
                v = is64 ? (int)e64[pos] : e32[pos]; \
            } \
            sI[(slot) * 128 + tid] = v; \
            if (which && v >= 0) atomicAdd(&g_cnt[v], 1.0f); \
        } \
    } while (0)

    #define GATHER_A3(aoff, tile) do { \
        int eb_ = (tile) * TM; \
        for (int idx = tid; idx < 1024; idx += BLK) { \
            int e = idx >> 4, k4 = (idx & 15) << 2; \
            long long eg = (long long)eb_ + e; \
            float4 x = make_float4(0.f, 0.f, 0.f, 0.f); \
            if (eg < (long long)E) x = *(const float4*)(edge_attr + eg * ED + k4); \
            __nv_bfloat162 p0 = __floats2bfloat162_rn(x.x, x.y); \
            __nv_bfloat162 p1 = __floats2bfloat162_rn(x.z, x.w); \
            uint2 u = make_uint2(*(uint32_t*)&p0, *(uint32_t*)&p1); \
            uint32_t off = (uint32_t)(e >> 3) * 1024u + (uint32_t)(e & 7) * 128u + (uint32_t)k4 * 2u; \
            *(uint2*)(sm + (aoff) + SW128(off)) = u; \
        } \
    } while (0)

    // prologue
    STAGE_IDX(0, bid);
    __syncthreads();
    GATHER_A3(E_A0, bid);
    if (nloc > 1) STAGE_IDX(1, bid + grid);
    __syncthreads();

    for (int L = 0; L < nloc; L++) {
        const int* sIL = sI + (L % 3) * 128;
        const uint32_t saAb = sbase + ((L & 1) ? E_A1 : E_A0);
        char* psb = sm + ((L & 1) ? E_PS1 : E_PS0);

        int dstA[2], dstB[2];
        #pragma unroll
        for (int i = 0; i < 2; i++) {
            int lr = 32 * rg + 16 * i + gg;
            dstA[i] = sIL[TM + lr];
            dstB[i] = sIL[TM + lr + 8];
        }

        // ---- a. PS stage: PS = P1[src] + P2[dst] (bf16 add), coalesced chunks ----
        {
            #pragma unroll
            for (int i = 0; i < 4; i++) {
                int e = ps_e0 + 16 * i;         // 0..63
                int src = sIL[e], dst = sIL[TM + e];
                if (src >= 0) {
                    uint4 a = *(const uint4*)(g_P1 + (size_t)src * 192 + ps_c * 8);
                    uint4 b = *(const uint4*)(g_P2 + (size_t)dst * 192 + ps_c * 8);
                    uint4 s;
                    s.x = hadd2u(a.x, b.x);
                    s.y = hadd2u(a.y, b.y);
                    s.z = hadd2u(a.z, b.z);
                    s.w = hadd2u(a.w, b.w);
                    *(uint4*)(psb + (uint32_t)e * PSROW + (uint32_t)ps_c * 16) = s;
                }
            }
        }

        // ---- b. MMA: z3 = A3 @ B3, K=64 ----
        float cgx[2][2][4], cm[2][2][4];
        #pragma unroll
        for (int i = 0; i < 2; i++)
            #pragma unroll
            for (int j = 0; j < 2; j++)
                #pragma unroll
                for (int c = 0; c < 4; c++) { cgx[i][j][c] = 0.f; cm[i][j][c] = 0.f; }

        uint32_t aBase[2], aSw[2];
        #pragma unroll
        for (int i = 0; i < 2; i++) {
            int e = 32 * rg + 16 * i + a_erow;
            aBase[i] = saAb + (uint32_t)(e >> 3) * 1024u + (uint32_t)(e & 7) * 128u;
            aSw[i] = (uint32_t)(e & 7);
        }
        #pragma unroll
        for (int kc = 0; kc < 4; kc++) {
            uint32_t kc2 = (uint32_t)(kc << 1);
            uint32_t aF[2][4], bg[4], bm[4];
            #pragma unroll
            for (int i = 0; i < 2; i++)
                ldsm_x4(aF[i], aBase[i] + (((kc2 | (uint32_t)a_khalf) ^ aSw[i]) << 4));
            ldsm_x4(bg, bgBase + (((kc2 | (uint32_t)b_khalf) ^ bgSw) << 4));
            ldsm_x4(bm, bmBase + (((kc2 | (uint32_t)b_khalf) ^ bmSw) << 4));
            #pragma unroll
            for (int i = 0; i < 2; i++) {
                mma16816(cgx[i][0], aF[i], bg);
                mma16816(cgx[i][1], aF[i], bg + 2);
                mma16816(cm[i][0], aF[i], bm);
                mma16816(cm[i][1], aF[i], bm + 2);
            }
        }

        // ---- c. stage next tile ----
        if (L + 1 < nloc) {
            GATHER_A3((L & 1) ? E_A0 : E_A1, bid + (L + 1) * grid);
            if (L + 2 < nloc) STAGE_IDX((L + 2) % 3, bid + (L + 2) * grid);
        }

        __syncthreads();   // d. single barrier: commits PS(L), A3(L+1), idx(L+2)

        // ---- e. epilogue: z = acc + PS; act; butterfly v4 RED ----
        #pragma unroll
        for (int i = 0; i < 2; i++) {
            int lr0 = 32 * rg + 16 * i + gg;
            int lr1 = lr0 + 8;
            int dst0 = dstA[i], dst1 = dstB[i];
            const char* r0p = psb + lr0 * PSROW;
            const char* r1p = psb + lr1 * PSROW;
            #pragma unroll
            for (int j = 0; j < 2; j++) {
                int c = ng0 + 8 * j + 2 * tt;
                float2 g0 = lds_bf2f(r0p + 2 * c);
                float2 m0 = lds_bf2f(r0p + 2 * c + 192);
                float2 g1 = lds_bf2f(r1p + 2 * c);
                float2 m1 = lds_bf2f(r1p + 2 * c + 192);
                float v00 = act_gm(cgx[i][j][0] + g0.x, cm[i][j][0] + m0.x);
                float v01 = act_gm(cgx[i][j][1] + g0.y, cm[i][j][1] + m0.y);
                float v10 = act_gm(cgx[i][j][2] + g1.x, cm[i][j][2] + m1.x);
                float v11 = act_gm(cgx[i][j][3] + g1.y, cm[i][j][3] + m1.y);
                float s0 = ttOdd ? v00 : v10;
                float s1 = ttOdd ? v01 : v11;
                float r0 = __shfl_xor_sync(0xffffffffu, s0, 1);
                float r1 = __shfl_xor_sync(0xffffffffu, s1, 1);
                int colbase = ng0 + 8 * j + (tt >> 1) * 4;
                if (!ttOdd) {
                    if (dst0 >= 0)
                        asm volatile("red.global.add.v4.f32 [%0], {%1,%2,%3,%4};"
                            :: "l"(out + (long long)dst0 * ND + colbase),
                               "f"(v00), "f"(v01), "f"(r0), "f"(r1) : "memory");
                } else {
                    if (dst1 >= 0)
                        asm volatile("red.global.add.v4.f32 [%0], {%1,%2,%3,%4};"
                            :: "l"(out + (long long)dst1 * ND + colbase),
                               "f"(r0), "f"(r1), "f"(v10), "f"(v11) : "memory");
                }
            }
        }
        // no trailing barrier: PS/A3 double-buffered, idx ring depth 3,
        // dst indices already registered before the mid-tile barrier.
    }
    #undef STAGE_IDX
    #undef GATHER_A3
}

extern "C" void kernel_launch(void* const* d_in, const int* in_sizes, int n_in,
                              void* d_out, int out_size) {
    const float* h   = (const float*)d_in[0];
    const void*  ei  = d_in[1];
    const float* ea  = (const float*)d_in[2];
    const float* W_e = (const float*)d_in[3];
    const float* b_e = (const float*)d_in[4];
    const float* W_n = (const float*)d_in[5];
    const float* b_n = (const float*)d_in[6];
    float* out = (float*)d_out;

    int N = in_sizes[0] / ND;
    int E = in_sizes[2] / ED;
    long long total4 = (long long)N * ND / 4;
    long long nwords = (long long)in_sizes[1];

    int ib = (int)((total4 + 255) / 256);
    init_kernel<<<ib, 256>>>((float4*)out, (const uint32_t*)ei, total4, N, nwords);

    int nblocks = (N + 63) / 64;
    cudaFuncSetAttribute(node_kernel, cudaFuncAttributeMaxDynamicSharedMemorySize, N_SMEM);
    node_kernel<<<nblocks, ABLK, N_SMEM>>>(h, W_e, b_e, W_n, b_n, N);

    int ntiles = (E + TM - 1) / TM;
    cudaFuncSetAttribute(edge_kernel, cudaFuncAttributeMaxDynamicSharedMemorySize, E_SMEM);
    int grid = ntiles < 296 ? ntiles : 296;
    edge_kernel<<<grid, BLK, E_SMEM>>>(ei, ea, W_e, W_n, out, E, ntiles);

    finalize_kernel<<<ib, 256>>>((const float4*)h, (float4*)out, total4);
}